// round 12
// baseline (speedup 1.0000x reference)
#include <cuda_runtime.h>
#include <cuda_bf16.h>
#include <math.h>
#include <stdint.h>

#define Nn 16384
#define Ee 262144
#define Cc 256
#define Rr 9
#define Bb 4
#define NK (Nn*Rr)
#define NCHUNK (NK/1024)
#define TILE_M 128
#define NPAIR (Rr*Rr)                 /* 81 */
#define TILES2 (Ee/TILE_M + NPAIR)    /* 2129 */

#define PADK 40                       /* padded bf16 cols per 32-col chunk row */
#define A_BYTES  (128*PADK*2)         /* 10240 */

/* edge kernel smem: A only, 2 stages */
#define SM2_ES   0
#define SM2_GSS  512
#define SM2_GSD  1024
#define SM2_BUF  2048
#define SM2_TOTAL (SM2_BUF + 2*A_BYTES)   /* 22528 */
/* g3 kernel smem: A only, 2 stages */
#define SM3_TOTAL (2*A_BYTES)             /* 20480 */

// ---------------- static scratch ----------------
__device__ __align__(16) __nv_bfloat16 g_Wt_hi[4][Rr*Cc*Cc]; // transposed [n][k]
__device__ __align__(16) __nv_bfloat16 g_nf_hi[(size_t)Nn*Cc];
__device__ __align__(16) __nv_bfloat16 g_relb[(size_t)Ee*Cc]; // bf16 mirror of rel_emb
__device__ float g_v[2][Rr*Cc];
__device__ float g_scores[2][Ee];
__device__ int   g_counts[2][NK];
__device__ int   g_rowptr[2][NK+1];
__device__ int   g_cursor[2][NK];
__device__ int   g_elist[2][Ee];
__device__ int   g_partials[2][NCHUNK];
__device__ __align__(16) __nv_bfloat16 g_Ph[2][(size_t)NK*Cc];
__device__ float g_invdiv[2][Nn];
__device__ int   g_pairCount[NPAIR];
__device__ int   g_pairStart[NPAIR+1];
__device__ int   g_tileStart2[NPAIR+1];
__device__ int   g_pairCursor[NPAIR];
__device__ int   g_perm2[Ee];
__device__ int4  g_tile[TILES2];

// ---------------- helpers ----------------
__device__ __forceinline__ uint32_t smem_u32(const void* p){
    return (uint32_t)__cvta_generic_to_shared((void*)p);
}
__device__ __forceinline__ void cpa16(uint32_t d, const void* s){
    asm volatile("cp.async.cg.shared.global [%0], [%1], 16;" :: "r"(d), "l"(s) : "memory");
}
__device__ __forceinline__ void cpa_commit(){
    asm volatile("cp.async.commit_group;" ::: "memory");
}
__device__ __forceinline__ void cpa_wait1(){
    asm volatile("cp.async.wait_group 1;" ::: "memory");
}
__device__ __forceinline__ void cpa_wait0(){
    asm volatile("cp.async.wait_group 0;" ::: "memory");
}
__device__ __forceinline__ void mma16816(float* c, const uint32_t* a, uint32_t b0, uint32_t b1){
    asm volatile("mma.sync.aligned.m16n8k16.row.col.f32.bf16.bf16.f32 "
        "{%0,%1,%2,%3}, {%4,%5,%6,%7}, {%8,%9}, {%0,%1,%2,%3};"
        : "+f"(c[0]), "+f"(c[1]), "+f"(c[2]), "+f"(c[3])
        : "r"(a[0]), "r"(a[1]), "r"(a[2]), "r"(a[3]), "r"(b0), "r"(b1));
}
__device__ __forceinline__ void ldsm4(uint32_t* r, uint32_t addr){
    asm volatile("ldmatrix.sync.aligned.m8n8.x4.shared.b16 {%0,%1,%2,%3}, [%4];"
        : "=r"(r[0]), "=r"(r[1]), "=r"(r[2]), "=r"(r[3]) : "r"(addr));
}

// ---------------- setup kernels ----------------
// merged: nf -> bf16, zero counts, zero pairCount
__global__ void k_initnf(const float* __restrict__ nf) {
    int i = blockIdx.x*256 + threadIdx.x;
    g_nf_hi[i] = __float2bfloat16(nf[i]);
    if (i < 2*NK) ((int*)g_counts)[i] = 0;
    if (i < NPAIR) g_pairCount[i] = 0;
}

// W^T bf16 directly from basis (bit-identical arithmetic to old k_w + k_wsplit)
__global__ void k_wtb(const float* b0, const float* a0, const float* b1, const float* a1,
                      const float* b2, const float* a2, const float* b3, const float* a3) {
    __shared__ float t[32][33];
    int bid = blockIdx.x;
    int br = bid / (Rr*64);
    int rem = bid % (Rr*64);
    int r = rem / 64, tile = rem % 64;
    int ti = (tile/8)*32, tj = (tile%8)*32;
    int lx = threadIdx.x & 31, ly = threadIdx.x >> 5;
    const float* bas = (br==0)?b0:(br==1)?b1:(br==2)?b2:b3;
    const float* att = (br==0)?a0:(br==1)?a1:(br==2)?a2:a3;
#pragma unroll
    for (int s = 0; s < 32; s += 8) {
        int i = ti+ly+s, j = tj+lx;
        float w = 0.f;
#pragma unroll
        for (int b = 0; b < Bb; b++) w += att[r*Bb+b]*bas[(b*Cc+i)*Cc + j];
        t[ly+s][lx] = w;
    }
    __syncthreads();
    __nv_bfloat16* Wh = g_Wt_hi[br] + r*Cc*Cc;
#pragma unroll
    for (int s = 0; s < 32; s += 8)
        Wh[(tj+ly+s)*Cc + ti+lx] = __float2bfloat16(t[lx][ly+s]);
}

// v directly from basis (bit-identical to old k_w + k_v)
__global__ void k_vb(const float* r2s_bas, const float* r2s_att, const float* r2s_aw,
                     const float* r2o_bas, const float* r2o_att, const float* r2o_aw) {
    int br = blockIdx.x / Rr, r = blockIdx.x % Rr;
    const float* bas = br ? r2o_bas : r2s_bas;
    const float* att = br ? r2o_att : r2s_att;
    const float* aw  = br ? r2o_aw  : r2s_aw;
    int i = threadIdx.x;
    float s = 0.f;
    for (int j = 0; j < Cc; j++) {
        float w = 0.f;
#pragma unroll
        for (int b = 0; b < Bb; b++) w += att[r*Bb+b]*bas[(b*Cc+i)*Cc + j];
        s += w*aw[r*Cc+j];
    }
    g_v[br][r*Cc+i] = s;
}

// pair hist + per-(node,rel) key counts
__global__ void k_hist(const int* src, const int* dst, const int* et_rel, const int* et_inv) {
    __shared__ int h[NPAIR];
    int tid = threadIdx.x;
    if (tid < NPAIR) h[tid] = 0;
    __syncthreads();
#pragma unroll
    for (int u = 0; u < 4; u++) {
        int e = blockIdx.x*1024 + u*256 + tid;
        int r1 = et_rel[e], r2 = et_inv[e];
        atomicAdd(&h[r1*Rr + r2], 1);
        atomicAdd(&g_counts[0][src[e]*Rr + r2], 1);
        atomicAdd(&g_counts[1][dst[e]*Rr + r1], 1);
    }
    __syncthreads();
    if (tid < NPAIR) atomicAdd(&g_pairCount[tid], h[tid]);
}

__global__ void k_smallscan() {
    if (threadIdx.x == 0) {
        int s = 0, t = 0;
        for (int p = 0; p < NPAIR; p++) {
            g_pairStart[p] = s; g_tileStart2[p] = t; g_pairCursor[p] = s;
            int c = g_pairCount[p];
            s += c; t += (c + TILE_M-1)/TILE_M;
        }
        g_pairStart[NPAIR] = s; g_tileStart2[NPAIR] = t;
    }
}

// per-tile LUT: (r1, r2, row0, rowEnd)
__global__ void k_tilefill() {
    int p = blockIdx.x;
    int r1 = p / Rr, r2 = p % Rr;
    int s0 = g_pairStart[p], s1 = g_pairStart[p+1];
    int t0 = g_tileStart2[p];
    int nt = (s1 - s0 + TILE_M-1)/TILE_M;
    for (int i = threadIdx.x; i < nt; i += blockDim.x)
        g_tile[t0+i] = make_int4(r1, r2, s0 + i*TILE_M, s1);
}

__global__ void k_binscatter(const int* et_rel, const int* et_inv) {
    __shared__ int h[NPAIR], base[NPAIR], loc[NPAIR];
    int tid = threadIdx.x;
    if (tid < NPAIR) { h[tid] = 0; loc[tid] = 0; }
    __syncthreads();
    int es[4], ps[4];
#pragma unroll
    for (int u = 0; u < 4; u++) {
        int e = blockIdx.x*1024 + u*256 + tid;
        es[u] = e; ps[u] = et_rel[e]*Rr + et_inv[e];
        atomicAdd(&h[ps[u]], 1);
    }
    __syncthreads();
    if (tid < NPAIR) base[tid] = atomicAdd(&g_pairCursor[tid], h[tid]);
    __syncthreads();
#pragma unroll
    for (int u = 0; u < 4; u++) {
        int p = base[ps[u]] + atomicAdd(&loc[ps[u]], 1);
        g_perm2[p] = es[u];
    }
}

__global__ void k_scan1() {
    int br = blockIdx.x / NCHUNK, ch = blockIdx.x % NCHUNK;
    int tid = threadIdx.x;
    int basei = ch*1024 + tid*4;
    int v[4]; int t = 0;
#pragma unroll
    for (int i = 0; i < 4; i++) { v[i] = g_counts[br][basei+i]; t += v[i]; }
    __shared__ int s[256];
    s[tid] = t; __syncthreads();
    for (int off = 1; off < 256; off <<= 1) {
        int x = (tid >= off) ? s[tid-off] : 0;
        __syncthreads();
        s[tid] += x;
        __syncthreads();
    }
    int excl = s[tid] - t;
#pragma unroll
    for (int i = 0; i < 4; i++) { g_rowptr[br][basei+i] = excl; excl += v[i]; }
    if (tid == 255) g_partials[br][ch] = s[255];
}

__global__ void k_scan2() {
    int br = threadIdx.x;
    if (br < 2) {
        int run = 0;
        for (int c = 0; c < NCHUNK; c++) { int p = g_partials[br][c]; g_partials[br][c] = run; run += p; }
        g_rowptr[br][NK] = run;
    }
}

__global__ void k_scan3() {
    int br = blockIdx.x / NCHUNK, ch = blockIdx.x % NCHUNK;
    int add = g_partials[br][ch];
    int basei = ch*1024 + threadIdx.x*4;
#pragma unroll
    for (int i = 0; i < 4; i++) {
        int p = g_rowptr[br][basei+i] + add;
        g_rowptr[br][basei+i] = p;
        g_cursor[br][basei+i] = p;
    }
}

__global__ void k_csrscatter(const int* src, const int* dst, const int* et_rel, const int* et_inv) {
    int e = blockIdx.x*256 + threadIdx.x;
    int k0 = src[e]*Rr + et_inv[e];
    g_elist[0][atomicAdd(&g_cursor[0][k0], 1)] = e;
    int k1 = dst[e]*Rr + et_rel[e];
    g_elist[1][atomicAdd(&g_cursor[1][k1], 1)] = e;
}

__global__ void k_invdiv() {
    int n = blockIdx.x*256 + threadIdx.x;
#pragma unroll
    for (int br = 0; br < 2; br++) {
        int c = 0;
        for (int r = 0; r < Rr; r++)
            if (g_rowptr[br][n*Rr+r+1] > g_rowptr[br][n*Rr+r]) c++;
        g_invdiv[br][n] = c ? 1.f/(float)c : 1.f;
    }
}

// ---------------- fused pair-binned edge GEMM + score ----------------
// rel = ef + 0.5*([nf[src],nf[dst]] @ [W0[r1];W1[r2]])  (K=512), fused leaky-relu scores
// A via cp.async+ldmatrix; B fragments LDG.32 direct from global (L2/L1-hot W)
__global__ void __launch_bounds__(512,1) k_edge(const int* __restrict__ src,
        const int* __restrict__ dst, const float* __restrict__ ef,
        float* __restrict__ rel_out,
        const float* __restrict__ bias_sub, const float* __restrict__ bias_obj) {
    extern __shared__ char smem[];
    int bx = blockIdx.x;
    if (bx >= g_tileStart2[NPAIR]) return;
    int4 tp = g_tile[bx];
    int r1 = tp.x, r2 = tp.y, row0 = tp.z, rowEnd = tp.w;

    int tid = threadIdx.x;
    int* es  = (int*)(smem + SM2_ES);
    int* gsS = (int*)(smem + SM2_GSS);
    int* gsD = (int*)(smem + SM2_GSD);
    if (tid < 128) {
        int row = row0 + tid;
        if (row < rowEnd) { int e = g_perm2[row]; es[tid] = e; gsS[tid] = src[e]; gsD[tid] = dst[e]; }
        else { es[tid] = -1; gsS[tid] = 0; gsD[tid] = 0; }
    }
    __syncthreads();

    const __nv_bfloat16* __restrict__ W1h = g_Wt_hi[0] + (size_t)r1*Cc*Cc;
    const __nv_bfloat16* __restrict__ W2h = g_Wt_hi[1] + (size_t)r2*Cc*Cc;

    auto load_chunk = [&](int ch, int st){
        __nv_bfloat16* AH = (__nv_bfloat16*)(smem + SM2_BUF + st*A_BYTES);
        int srcside = ch < 8;
        int k0 = (ch & 7)*32;
        int row = tid >> 2, c16 = tid & 3;
        int node = srcside ? gsS[row] : gsD[row];
        cpa16(smem_u32(AH + row*PADK + c16*8), g_nf_hi + (size_t)node*Cc + k0 + c16*8);
        cpa_commit();
    };

    int lane = tid & 31, wid = tid >> 5;
    int gid = lane >> 2, tig = lane & 3;
    int wm = wid & 3, wn = wid >> 2;

    int a_row = (lane & 15);
    int a_koff = (lane >> 4) << 3;

    float acc[2][8][4];
#pragma unroll
    for (int mt = 0; mt < 2; mt++)
#pragma unroll
        for (int nt = 0; nt < 8; nt++)
#pragma unroll
            for (int q = 0; q < 4; q++) acc[mt][nt][q] = 0.f;

    load_chunk(0, 0);
    for (int ch = 0; ch < 16; ch++) {
        if (ch < 15) { load_chunk(ch+1, (ch+1)&1); cpa_wait1(); }
        else cpa_wait0();
        __syncthreads();
        uint32_t aA = smem_u32(smem + SM2_BUF + (ch&1)*A_BYTES);
        const __nv_bfloat16* __restrict__ Wb = (ch < 8) ? W1h : W2h;
        int k0 = (ch & 7)*32;
#pragma unroll
        for (int ks = 0; ks < 2; ks++) {
            uint32_t ah[2][4];
#pragma unroll
            for (int mt = 0; mt < 2; mt++)
                ldsm4(ah[mt], aA + ((wm*32 + mt*16 + a_row)*PADK + ks*16 + a_koff)*2);
            int kg = k0 + ks*16 + 2*tig;
            uint32_t bb[8][2];
#pragma unroll
            for (int nt = 0; nt < 8; nt++) {
                const __nv_bfloat16* wp = Wb + (size_t)(wn*64 + nt*8 + gid)*Cc + kg;
                bb[nt][0] = *(const uint32_t*)wp;
                bb[nt][1] = *(const uint32_t*)(wp + 8);
            }
#pragma unroll
            for (int nt = 0; nt < 8; nt++)
#pragma unroll
                for (int mt = 0; mt < 2; mt++)
                    mma16816(acc[mt][nt], ah[mt], bb[nt][0], bb[nt][1]);
        }
        __syncthreads();
    }

    // epilogue: rel write (fp32 + bf16 mirror) + fused scores
    float* sc0 = (float*)(smem + SM2_BUF);
    float* sc1 = sc0 + 128;
    if (tid < 128) { sc0[tid] = 0.f; sc1[tid] = 0.f; }
    __syncthreads();

    const float* vs = g_v[0] + r2*Cc;
    const float* vo = g_v[1] + r1*Cc;
    int cbase = wn*64 + 2*tig;
#pragma unroll
    for (int mt = 0; mt < 2; mt++)
#pragma unroll
        for (int h = 0; h < 2; h++) {
            int row = wm*32 + mt*16 + h*8 + gid;
            int e = es[row];
            float s0 = 0.f, s1 = 0.f;
            if (e >= 0) {
                float* op = rel_out + (size_t)e*Cc + cbase;
                const float* efp = ef + (size_t)e*Cc + cbase;
                __nv_bfloat16* rb = g_relb + (size_t)e*Cc + cbase;
#pragma unroll
                for (int nt = 0; nt < 8; nt++) {
                    int c = cbase + nt*8;
                    float2 e2 = *(const float2*)(efp + nt*8);
                    float wx = e2.x + 0.5f*acc[mt][nt][h*2+0];
                    float wy = e2.y + 0.5f*acc[mt][nt][h*2+1];
                    *(float2*)(op + nt*8) = make_float2(wx, wy);
                    *(__nv_bfloat162*)(rb + nt*8) = __floats2bfloat162_rn(wx, wy);
                    s0 += wx*vs[c] + wy*vs[c+1];
                    s1 += wx*vo[c] + wy*vo[c+1];
                }
            }
            s0 += __shfl_xor_sync(0xffffffffu, s0, 1);
            s0 += __shfl_xor_sync(0xffffffffu, s0, 2);
            s1 += __shfl_xor_sync(0xffffffffu, s1, 1);
            s1 += __shfl_xor_sync(0xffffffffu, s1, 2);
            if (tig == 0 && e >= 0) {
                atomicAdd(&sc0[row], s0);
                atomicAdd(&sc1[row], s1);
            }
        }
    __syncthreads();
    if (tid < 128) {
        int e = es[tid];
        if (e >= 0) {
            float a = sc0[tid] + bias_sub[r2]; a = (a >= 0.f) ? a : 0.01f*a;
            float b = sc1[tid] + bias_obj[r1]; b = (b >= 0.f) ? b : 0.01f*b;
            g_scores[0][e] = a;
            g_scores[1][e] = b;
        }
    }
}

// P fill (both branches): invdiv-scaled softmax-weighted sums from bf16 rel, single pass
__global__ void k_pfill() {
    int w = blockIdx.x*8 + (threadIdx.x >> 5);
    int lane = threadIdx.x & 31;
    int br = (w >= NK) ? 1 : 0;
    int key = w - br*NK;
    if (w >= 2*NK) return;
    int lo = g_rowptr[br][key], hi = g_rowptr[br][key+1];
    float2 acc[4];
#pragma unroll
    for (int j = 0; j < 4; j++) acc[j] = make_float2(0.f, 0.f);
    if (lo < hi) {
        float den = 0.f;
        for (int p = lo; p < hi; p++) {
            int e = g_elist[br][p];
            float wt = expf(g_scores[br][e]);
            den += wt;
            const __nv_bfloat162* x = (const __nv_bfloat162*)(g_relb + (size_t)e*Cc);
#pragma unroll
            for (int j = 0; j < 4; j++) {
                __nv_bfloat162 v = x[lane + 32*j];
                acc[j].x += wt*__low2float(v);
                acc[j].y += wt*__high2float(v);
            }
        }
        float inv = g_invdiv[br][key/Rr]/den;
#pragma unroll
        for (int j = 0; j < 4; j++) { acc[j].x *= inv; acc[j].y *= inv; }
    }
    __nv_bfloat162* Ph = (__nv_bfloat162*)(g_Ph[br] + (size_t)key*Cc);
#pragma unroll
    for (int j = 0; j < 4; j++) Ph[lane + 32*j] = __floats2bfloat162_rn(acc[j].x, acc[j].y);
}

// ---------------- fused agg GEMM: out = nf + 0.5*([P0,P1] @ [W2;W3])  (K=4608) ----------------
// A via cp.async+ldmatrix; B fragments LDG.32 direct from global
__global__ void __launch_bounds__(512,1) k_g3(const float* __restrict__ nf,
                                              float* __restrict__ node_out) {
    extern __shared__ char smem[];
    int n0 = blockIdx.x*TILE_M;
    int tid = threadIdx.x;

    auto load_chunk = [&](int ch, int st){
        __nv_bfloat16* AH = (__nv_bfloat16*)(smem + st*A_BYTES);
        int brs = ch >= 72;
        int kk = (brs ? ch-72 : ch)*32;
        int row = tid >> 2, c16 = tid & 3;
        cpa16(smem_u32(AH + row*PADK + c16*8),
              g_Ph[brs] + (size_t)(n0+row)*(Rr*Cc) + kk + c16*8);
        cpa_commit();
    };

    int lane = tid & 31, wid = tid >> 5;
    int gid = lane >> 2, tig = lane & 3;
    int wm = wid & 3, wn = wid >> 2;

    int a_row = (lane & 15);
    int a_koff = (lane >> 4) << 3;

    float acc[2][8][4];
#pragma unroll
    for (int mt = 0; mt < 2; mt++)
#pragma unroll
        for (int nt = 0; nt < 8; nt++)
#pragma unroll
            for (int q = 0; q < 4; q++) acc[mt][nt][q] = 0.f;

    const int NCH = 144;
    load_chunk(0, 0);
    for (int ch = 0; ch < NCH; ch++) {
        if (ch < NCH-1) { load_chunk(ch+1, (ch+1)&1); cpa_wait1(); }
        else cpa_wait0();
        __syncthreads();
        uint32_t aA = smem_u32(smem + (ch&1)*A_BYTES);
        int brs = ch >= 72;
        int kk = (brs ? ch-72 : ch)*32;
        int rb = kk >> 8, c0 = kk & 255;
        const __nv_bfloat16* __restrict__ Wb = g_Wt_hi[2+brs] + (size_t)rb*Cc*Cc;
#pragma unroll
        for (int ks = 0; ks < 2; ks++) {
            uint32_t ah[2][4];
#pragma unroll
            for (int mt = 0; mt < 2; mt++)
                ldsm4(ah[mt], aA + ((wm*32 + mt*16 + a_row)*PADK + ks*16 + a_koff)*2);
            int kg = c0 + ks*16 + 2*tig;
            uint32_t bb[8][2];
#pragma unroll
            for (int nt = 0; nt < 8; nt++) {
                const __nv_bfloat16* wp = Wb + (size_t)(wn*64 + nt*8 + gid)*Cc + kg;
                bb[nt][0] = *(const uint32_t*)wp;
                bb[nt][1] = *(const uint32_t*)(wp + 8);
            }
#pragma unroll
            for (int nt = 0; nt < 8; nt++)
#pragma unroll
                for (int mt = 0; mt < 2; mt++)
                    mma16816(acc[mt][nt], ah[mt], bb[nt][0], bb[nt][1]);
        }
        __syncthreads();
    }

    int cbase = wn*64 + 2*tig;
#pragma unroll
    for (int mt = 0; mt < 2; mt++)
#pragma unroll
        for (int h = 0; h < 2; h++) {
            int n = n0 + wm*32 + mt*16 + h*8 + gid;
            float* op = node_out + (size_t)n*Cc + cbase;
            const float* nfp = nf + (size_t)n*Cc + cbase;
#pragma unroll
            for (int nt = 0; nt < 8; nt++) {
                float2 b2 = *(const float2*)(nfp + nt*8);
                float2 w;
                w.x = b2.x + 0.5f*acc[mt][nt][h*2+0];
                w.y = b2.y + 0.5f*acc[mt][nt][h*2+1];
                *(float2*)(op + nt*8) = w;
            }
        }
}

extern "C" void kernel_launch(void* const* d_in, const int* in_sizes, int n_in,
                              void* d_out, int out_size) {
    const int* ei      = (const int*)d_in[0];
    const int* src     = ei;
    const int* dst     = ei + Ee;
    const float* nf    = (const float*)d_in[1];
    const float* ef    = (const float*)d_in[2];
    const int* et_rel  = (const int*)d_in[3];
    const int* et_inv  = (const int*)d_in[4];
    const float* s2r_b = (const float*)d_in[6];
    const float* s2r_a = (const float*)d_in[7];
    const float* o2r_b = (const float*)d_in[8];
    const float* o2r_a = (const float*)d_in[9];
    const float* r2s_b = (const float*)d_in[10];
    const float* r2s_a = (const float*)d_in[11];
    const float* r2s_w = (const float*)d_in[12];
    const float* r2s_bias = (const float*)d_in[13];
    const float* r2o_b = (const float*)d_in[14];
    const float* r2o_a = (const float*)d_in[15];
    const float* r2o_w = (const float*)d_in[16];
    const float* r2o_bias = (const float*)d_in[17];

    float* node_out = (float*)d_out;
    float* rel_out  = node_out + (size_t)Nn*Cc;

    cudaFuncSetAttribute(k_edge, cudaFuncAttributeMaxDynamicSharedMemorySize, SM2_TOTAL);
    cudaFuncSetAttribute(k_g3, cudaFuncAttributeMaxDynamicSharedMemorySize, SM3_TOTAL);

    k_initnf<<<(Nn*Cc)/256, 256>>>(nf);
    k_wtb<<<4*Rr*64, 256>>>(s2r_b, s2r_a, o2r_b, o2r_a, r2s_b, r2s_a, r2o_b, r2o_a);
    k_vb<<<2*Rr, 256>>>(r2s_b, r2s_a, r2s_w, r2o_b, r2o_a, r2o_w);
    k_hist<<<256, 256>>>(src, dst, et_rel, et_inv);
    k_smallscan<<<1, 32>>>();
    k_tilefill<<<NPAIR, 128>>>();
    k_binscatter<<<256, 256>>>(et_rel, et_inv);
    k_scan1<<<2*NCHUNK, 256>>>();
    k_scan2<<<1, 32>>>();
    k_scan3<<<2*NCHUNK, 256>>>();
    k_csrscatter<<<Ee/256, 256>>>(src, dst, et_rel, et_inv);
    k_invdiv<<<Nn/256, 256>>>();

    k_edge<<<TILES2, 512, SM2_TOTAL>>>(src, dst, ef, rel_out, r2s_bias, r2o_bias);
    k_pfill<<<2*NK/8, 256>>>();
    k_g3<<<Nn/TILE_M, 512, SM3_TOTAL>>>(nf, node_out);
}

// round 13
// speedup vs baseline: 1.7528x; 1.7528x over previous
#include <cuda_runtime.h>
#include <cuda_bf16.h>
#include <math.h>
#include <stdint.h>

#define Nn 16384
#define Ee 262144
#define Cc 256
#define Rr 9
#define Bb 4
#define NK (Nn*Rr)
#define NCHUNK (NK/1024)
#define TILE_M 128
#define NPAIR (Rr*Rr)                 /* 81 */
#define TILES2 (Ee/TILE_M + NPAIR)    /* 2129 */

#define PADK 40                       /* padded bf16 cols per 32-col chunk row */

#define A_BYTES  (128*PADK*2)         /* 10240 */
#define B_BYTES  (256*PADK*2)         /* 20480 */

/* edge kernel smem: AH+BH per stage, 3 stages */
#define SM2_ES   0
#define SM2_GSS  512
#define SM2_GSD  1024
#define SM2_BUF  2048
#define SSTRIDE_E (A_BYTES + B_BYTES)      /* 30720 */
#define SM2_TOTAL (SM2_BUF + 3*SSTRIDE_E)  /* 94208 */

/* g3 kernel smem: AH+BH per stage, 3 stages */
#define SSTRIDE_G (A_BYTES + B_BYTES)      /* 30720 */
#define SM3_TOTAL (3*SSTRIDE_G)            /* 92160 */

// ---------------- static scratch ----------------
__device__ __align__(16) __nv_bfloat16 g_Wt_hi[4][Rr*Cc*Cc]; // transposed [n][k]
__device__ __align__(16) __nv_bfloat16 g_nf_hi[(size_t)Nn*Cc];
__device__ __align__(16) __nv_bfloat16 g_relb[(size_t)Ee*Cc]; // bf16 mirror of rel_emb
__device__ float g_v[2][Rr*Cc];
__device__ float g_scores[2][Ee];
__device__ int   g_counts[2][NK];
__device__ int   g_rowptr[2][NK+1];
__device__ int   g_cursor[2][NK];
__device__ int   g_elist[2][Ee];
__device__ int   g_partials[2][NCHUNK];
__device__ __align__(16) __nv_bfloat16 g_Ph[2][(size_t)NK*Cc];
__device__ float g_invdiv[2][Nn];
__device__ int   g_pairCount[NPAIR];
__device__ int   g_pairStart[NPAIR+1];
__device__ int   g_tileStart2[NPAIR+1];
__device__ int   g_pairCursor[NPAIR];
__device__ int   g_perm2[Ee];
__device__ int4  g_tile[TILES2];

// ---------------- helpers ----------------
__device__ __forceinline__ uint32_t smem_u32(const void* p){
    return (uint32_t)__cvta_generic_to_shared((void*)p);
}
__device__ __forceinline__ void cpa16(uint32_t d, const void* s){
    asm volatile("cp.async.cg.shared.global [%0], [%1], 16;" :: "r"(d), "l"(s) : "memory");
}
__device__ __forceinline__ void cpa_commit(){
    asm volatile("cp.async.commit_group;" ::: "memory");
}
__device__ __forceinline__ void cpa_wait2(){
    asm volatile("cp.async.wait_group 2;" ::: "memory");
}
__device__ __forceinline__ void cpa_wait1(){
    asm volatile("cp.async.wait_group 1;" ::: "memory");
}
__device__ __forceinline__ void cpa_wait0(){
    asm volatile("cp.async.wait_group 0;" ::: "memory");
}
__device__ __forceinline__ void mma16816(float* c, const uint32_t* a, uint32_t b0, uint32_t b1){
    asm volatile("mma.sync.aligned.m16n8k16.row.col.f32.bf16.bf16.f32 "
        "{%0,%1,%2,%3}, {%4,%5,%6,%7}, {%8,%9}, {%0,%1,%2,%3};"
        : "+f"(c[0]), "+f"(c[1]), "+f"(c[2]), "+f"(c[3])
        : "r"(a[0]), "r"(a[1]), "r"(a[2]), "r"(a[3]), "r"(b0), "r"(b1));
}
__device__ __forceinline__ void ldsm4(uint32_t* r, uint32_t addr){
    asm volatile("ldmatrix.sync.aligned.m8n8.x4.shared.b16 {%0,%1,%2,%3}, [%4];"
        : "=r"(r[0]), "=r"(r[1]), "=r"(r[2]), "=r"(r[3]) : "r"(addr));
}

// ---------------- setup kernels ----------------
// merged: nf -> bf16, zero counts, zero pairCount
__global__ void k_initnf(const float* __restrict__ nf) {
    int i = blockIdx.x*256 + threadIdx.x;
    g_nf_hi[i] = __float2bfloat16(nf[i]);
    if (i < 2*NK) ((int*)g_counts)[i] = 0;
    if (i < NPAIR) g_pairCount[i] = 0;
}

// W^T bf16 directly from basis (bit-identical arithmetic to fp32 staging path)
__global__ void k_wtb(const float* b0, const float* a0, const float* b1, const float* a1,
                      const float* b2, const float* a2, const float* b3, const float* a3) {
    __shared__ float t[32][33];
    int bid = blockIdx.x;
    int br = bid / (Rr*64);
    int rem = bid % (Rr*64);
    int r = rem / 64, tile = rem % 64;
    int ti = (tile/8)*32, tj = (tile%8)*32;
    int lx = threadIdx.x & 31, ly = threadIdx.x >> 5;
    const float* bas = (br==0)?b0:(br==1)?b1:(br==2)?b2:b3;
    const float* att = (br==0)?a0:(br==1)?a1:(br==2)?a2:a3;
#pragma unroll
    for (int s = 0; s < 32; s += 8) {
        int i = ti+ly+s, j = tj+lx;
        float w = 0.f;
#pragma unroll
        for (int b = 0; b < Bb; b++) w += att[r*Bb+b]*bas[(b*Cc+i)*Cc + j];
        t[ly+s][lx] = w;
    }
    __syncthreads();
    __nv_bfloat16* Wh = g_Wt_hi[br] + r*Cc*Cc;
#pragma unroll
    for (int s = 0; s < 32; s += 8)
        Wh[(tj+ly+s)*Cc + ti+lx] = __float2bfloat16(t[lx][ly+s]);
}

// v directly from basis
__global__ void k_vb(const float* r2s_bas, const float* r2s_att, const float* r2s_aw,
                     const float* r2o_bas, const float* r2o_att, const float* r2o_aw) {
    int br = blockIdx.x / Rr, r = blockIdx.x % Rr;
    const float* bas = br ? r2o_bas : r2s_bas;
    const float* att = br ? r2o_att : r2s_att;
    const float* aw  = br ? r2o_aw  : r2s_aw;
    int i = threadIdx.x;
    float s = 0.f;
    for (int j = 0; j < Cc; j++) {
        float w = 0.f;
#pragma unroll
        for (int b = 0; b < Bb; b++) w += att[r*Bb+b]*bas[(b*Cc+i)*Cc + j];
        s += w*aw[r*Cc+j];
    }
    g_v[br][r*Cc+i] = s;
}

// pair hist + per-(node,rel) key counts
__global__ void k_hist(const int* src, const int* dst, const int* et_rel, const int* et_inv) {
    __shared__ int h[NPAIR];
    int tid = threadIdx.x;
    if (tid < NPAIR) h[tid] = 0;
    __syncthreads();
#pragma unroll
    for (int u = 0; u < 4; u++) {
        int e = blockIdx.x*1024 + u*256 + tid;
        int r1 = et_rel[e], r2 = et_inv[e];
        atomicAdd(&h[r1*Rr + r2], 1);
        atomicAdd(&g_counts[0][src[e]*Rr + r2], 1);
        atomicAdd(&g_counts[1][dst[e]*Rr + r1], 1);
    }
    __syncthreads();
    if (tid < NPAIR) atomicAdd(&g_pairCount[tid], h[tid]);
}

__global__ void k_smallscan() {
    if (threadIdx.x == 0) {
        int s = 0, t = 0;
        for (int p = 0; p < NPAIR; p++) {
            g_pairStart[p] = s; g_tileStart2[p] = t; g_pairCursor[p] = s;
            int c = g_pairCount[p];
            s += c; t += (c + TILE_M-1)/TILE_M;
        }
        g_pairStart[NPAIR] = s; g_tileStart2[NPAIR] = t;
    }
}

// per-tile LUT: (r1, r2, row0, rowEnd)
__global__ void k_tilefill() {
    int p = blockIdx.x;
    int r1 = p / Rr, r2 = p % Rr;
    int s0 = g_pairStart[p], s1 = g_pairStart[p+1];
    int t0 = g_tileStart2[p];
    int nt = (s1 - s0 + TILE_M-1)/TILE_M;
    for (int i = threadIdx.x; i < nt; i += blockDim.x)
        g_tile[t0+i] = make_int4(r1, r2, s0 + i*TILE_M, s1);
}

__global__ void k_binscatter(const int* et_rel, const int* et_inv) {
    __shared__ int h[NPAIR], base[NPAIR], loc[NPAIR];
    int tid = threadIdx.x;
    if (tid < NPAIR) { h[tid] = 0; loc[tid] = 0; }
    __syncthreads();
    int es[4], ps[4];
#pragma unroll
    for (int u = 0; u < 4; u++) {
        int e = blockIdx.x*1024 + u*256 + tid;
        es[u] = e; ps[u] = et_rel[e]*Rr + et_inv[e];
        atomicAdd(&h[ps[u]], 1);
    }
    __syncthreads();
    if (tid < NPAIR) base[tid] = atomicAdd(&g_pairCursor[tid], h[tid]);
    __syncthreads();
#pragma unroll
    for (int u = 0; u < 4; u++) {
        int p = base[ps[u]] + atomicAdd(&loc[ps[u]], 1);
        g_perm2[p] = es[u];
    }
}

__global__ void k_scan1() {
    int br = blockIdx.x / NCHUNK, ch = blockIdx.x % NCHUNK;
    int tid = threadIdx.x;
    int basei = ch*1024 + tid*4;
    int v[4]; int t = 0;
#pragma unroll
    for (int i = 0; i < 4; i++) { v[i] = g_counts[br][basei+i]; t += v[i]; }
    __shared__ int s[256];
    s[tid] = t; __syncthreads();
    for (int off = 1; off < 256; off <<= 1) {
        int x = (tid >= off) ? s[tid-off] : 0;
        __syncthreads();
        s[tid] += x;
        __syncthreads();
    }
    int excl = s[tid] - t;
#pragma unroll
    for (int i = 0; i < 4; i++) { g_rowptr[br][basei+i] = excl; excl += v[i]; }
    if (tid == 255) g_partials[br][ch] = s[255];
}

__global__ void k_scan2() {
    int br = threadIdx.x;
    if (br < 2) {
        int run = 0;
        for (int c = 0; c < NCHUNK; c++) { int p = g_partials[br][c]; g_partials[br][c] = run; run += p; }
        g_rowptr[br][NK] = run;
    }
}

__global__ void k_scan3() {
    int br = blockIdx.x / NCHUNK, ch = blockIdx.x % NCHUNK;
    int add = g_partials[br][ch];
    int basei = ch*1024 + threadIdx.x*4;
#pragma unroll
    for (int i = 0; i < 4; i++) {
        int p = g_rowptr[br][basei+i] + add;
        g_rowptr[br][basei+i] = p;
        g_cursor[br][basei+i] = p;
    }
}

__global__ void k_csrscatter(const int* src, const int* dst, const int* et_rel, const int* et_inv) {
    int e = blockIdx.x*256 + threadIdx.x;
    int k0 = src[e]*Rr + et_inv[e];
    g_elist[0][atomicAdd(&g_cursor[0][k0], 1)] = e;
    int k1 = dst[e]*Rr + et_rel[e];
    g_elist[1][atomicAdd(&g_cursor[1][k1], 1)] = e;
}

__global__ void k_invdiv() {
    int n = blockIdx.x*256 + threadIdx.x;
#pragma unroll
    for (int br = 0; br < 2; br++) {
        int c = 0;
        for (int r = 0; r < Rr; r++)
            if (g_rowptr[br][n*Rr+r+1] > g_rowptr[br][n*Rr+r]) c++;
        g_invdiv[br][n] = c ? 1.f/(float)c : 1.f;
    }
}

// ---------------- fused pair-binned edge GEMM + score ----------------
// rel = ef + 0.5*([nf[src],nf[dst]] @ [W0[r1];W1[r2]])  (K=512), fused leaky-relu scores
// single-pass bf16, cp.async staging (A+B), ldmatrix frags, 3-stage pipeline
__global__ void __launch_bounds__(512,1) k_edge(const int* __restrict__ src,
        const int* __restrict__ dst, const float* __restrict__ ef,
        float* __restrict__ rel_out,
        const float* __restrict__ bias_sub, const float* __restrict__ bias_obj) {
    extern __shared__ char smem[];
    int bx = blockIdx.x;
    if (bx >= g_tileStart2[NPAIR]) return;
    int4 tp = g_tile[bx];
    int r1 = tp.x, r2 = tp.y, row0 = tp.z, rowEnd = tp.w;

    int tid = threadIdx.x;
    int* es  = (int*)(smem + SM2_ES);
    int* gsS = (int*)(smem + SM2_GSS);
    int* gsD = (int*)(smem + SM2_GSD);
    if (tid < 128) {
        int row = row0 + tid;
        if (row < rowEnd) { int e = g_perm2[row]; es[tid] = e; gsS[tid] = src[e]; gsD[tid] = dst[e]; }
        else { es[tid] = -1; gsS[tid] = 0; gsD[tid] = 0; }
    }
    __syncthreads();

    const __nv_bfloat16* __restrict__ W1h = g_Wt_hi[0] + (size_t)r1*Cc*Cc;
    const __nv_bfloat16* __restrict__ W2h = g_Wt_hi[1] + (size_t)r2*Cc*Cc;

    auto load_chunk = [&](int ch){
        char* base = smem + SM2_BUF + (ch%3)*SSTRIDE_E;
        __nv_bfloat16* AH = (__nv_bfloat16*)base;
        __nv_bfloat16* BH = (__nv_bfloat16*)(base + A_BYTES);
        int srcside = ch < 8;
        int k0 = (ch & 7)*32;
        {
            int row = tid >> 2, c16 = tid & 3;
            int node = srcside ? gsS[row] : gsD[row];
            cpa16(smem_u32(AH + row*PADK + c16*8), g_nf_hi + (size_t)node*Cc + k0 + c16*8);
        }
        const __nv_bfloat16* Wh = srcside ? W1h : W2h;
#pragma unroll
        for (int it = 0; it < 2; it++) {
            int i = it*512 + tid; int row = i >> 2, c16 = i & 3;
            cpa16(smem_u32(BH + row*PADK + c16*8), Wh + (size_t)row*Cc + k0 + c16*8);
        }
        cpa_commit();
    };

    int lane = tid & 31, wid = tid >> 5;
    int gid = lane >> 2, tig = lane & 3;
    int wm = wid & 3, wn = wid >> 2;

    int a_row = (lane & 15);
    int a_koff = (lane >> 4) << 3;
    int b_row = (lane & 7) + (((lane >> 4) & 1) << 3);
    int b_koff = ((lane >> 3) & 1) << 3;

    float acc[2][8][4];
#pragma unroll
    for (int mt = 0; mt < 2; mt++)
#pragma unroll
        for (int nt = 0; nt < 8; nt++)
#pragma unroll
            for (int q = 0; q < 4; q++) acc[mt][nt][q] = 0.f;

    load_chunk(0);
    load_chunk(1);
    for (int ch = 0; ch < 16; ch++) {
        if (ch + 2 < 16) { load_chunk(ch+2); cpa_wait2(); }
        else if (ch + 1 < 16) cpa_wait1();
        else cpa_wait0();
        __syncthreads();
        char* base = smem + SM2_BUF + (ch%3)*SSTRIDE_E;
        uint32_t aA = smem_u32(base);
        uint32_t aB = smem_u32(base + A_BYTES);
#pragma unroll
        for (int ks = 0; ks < 2; ks++) {
            int kc = ks*16;
            uint32_t ah[2][4];
#pragma unroll
            for (int mt = 0; mt < 2; mt++)
                ldsm4(ah[mt], aA + ((wm*32 + mt*16 + a_row)*PADK + kc + a_koff)*2);
            uint32_t bb[8][2];
#pragma unroll
            for (int ntp = 0; ntp < 4; ntp++) {
                uint32_t r[4];
                ldsm4(r, aB + ((wn*64 + ntp*16 + b_row)*PADK + kc + b_koff)*2);
                bb[2*ntp][0] = r[0]; bb[2*ntp][1] = r[1];
                bb[2*ntp+1][0] = r[2]; bb[2*ntp+1][1] = r[3];
            }
#pragma unroll
            for (int nt = 0; nt < 8; nt++)
#pragma unroll
                for (int mt = 0; mt < 2; mt++)
                    mma16816(acc[mt][nt], ah[mt], bb[nt][0], bb[nt][1]);
        }
        __syncthreads();
    }

    // epilogue: rel write (fp32 + bf16 mirror) + fused scores
    float* sc0 = (float*)(smem + SM2_BUF);
    float* sc1 = sc0 + 128;
    if (tid < 128) { sc0[tid] = 0.f; sc1[tid] = 0.f; }
    __syncthreads();

    const float* vs = g_v[0] + r2*Cc;
    const float* vo = g_v[1] + r1*Cc;
    int cbase = wn*64 + 2*tig;
#pragma unroll
    for (int mt = 0; mt < 2; mt++)
#pragma unroll
        for (int h = 0; h < 2; h++) {
            int row = wm*32 + mt*16 + h*8 + gid;
            int e = es[row];
            float s0 = 0.f, s1 = 0.f;
            if (e >= 0) {
                float* op = rel_out + (size_t)e*Cc + cbase;
                const float* efp = ef + (size_t)e*Cc + cbase;
                __nv_bfloat16* rb = g_relb + (size_t)e*Cc + cbase;
#pragma unroll
                for (int nt = 0; nt < 8; nt++) {
                    int c = cbase + nt*8;
                    float2 e2 = *(const float2*)(efp + nt*8);
                    float wx = e2.x + 0.5f*acc[mt][nt][h*2+0];
                    float wy = e2.y + 0.5f*acc[mt][nt][h*2+1];
                    *(float2*)(op + nt*8) = make_float2(wx, wy);
                    *(__nv_bfloat162*)(rb + nt*8) = __floats2bfloat162_rn(wx, wy);
                    s0 += wx*vs[c] + wy*vs[c+1];
                    s1 += wx*vo[c] + wy*vo[c+1];
                }
            }
            s0 += __shfl_xor_sync(0xffffffffu, s0, 1);
            s0 += __shfl_xor_sync(0xffffffffu, s0, 2);
            s1 += __shfl_xor_sync(0xffffffffu, s1, 1);
            s1 += __shfl_xor_sync(0xffffffffu, s1, 2);
            if (tig == 0 && e >= 0) {
                atomicAdd(&sc0[row], s0);
                atomicAdd(&sc1[row], s1);
            }
        }
    __syncthreads();
    if (tid < 128) {
        int e = es[tid];
        if (e >= 0) {
            float a = sc0[tid] + bias_sub[r2]; a = (a >= 0.f) ? a : 0.01f*a;
            float b = sc1[tid] + bias_obj[r1]; b = (b >= 0.f) ? b : 0.01f*b;
            g_scores[0][e] = a;
            g_scores[1][e] = b;
        }
    }
}

// P fill (both branches): invdiv-scaled softmax-weighted sums from bf16 rel, single pass
__global__ void k_pfill() {
    int w = blockIdx.x*8 + (threadIdx.x >> 5);
    int lane = threadIdx.x & 31;
    int br = (w >= NK) ? 1 : 0;
    int key = w - br*NK;
    if (w >= 2*NK) return;
    int lo = g_rowptr[br][key], hi = g_rowptr[br][key+1];
    float2 acc[4];
#pragma unroll
    for (int j = 0; j < 4; j++) acc[j] = make_float2(0.f, 0.f);
    if (lo < hi) {
        float den = 0.f;
        for (int p = lo; p < hi; p++) {
            int e = g_elist[br][p];
            float wt = expf(g_scores[br][e]);
            den += wt;
            const __nv_bfloat162* x = (const __nv_bfloat162*)(g_relb + (size_t)e*Cc);
#pragma unroll
            for (int j = 0; j < 4; j++) {
                __nv_bfloat162 v = x[lane + 32*j];
                acc[j].x += wt*__low2float(v);
                acc[j].y += wt*__high2float(v);
            }
        }
        float inv = g_invdiv[br][key/Rr]/den;
#pragma unroll
        for (int j = 0; j < 4; j++) { acc[j].x *= inv; acc[j].y *= inv; }
    }
    __nv_bfloat162* Ph = (__nv_bfloat162*)(g_Ph[br] + (size_t)key*Cc);
#pragma unroll
    for (int j = 0; j < 4; j++) Ph[lane + 32*j] = __floats2bfloat162_rn(acc[j].x, acc[j].y);
}

// ---------------- fused agg GEMM: out = nf + 0.5*([P0,P1] @ [W2;W3])  (K=4608) ----------------
// single-pass bf16, cp.async staging (A+B), ldmatrix frags, 3-stage pipeline
__global__ void __launch_bounds__(512,1) k_g3(const float* __restrict__ nf,
                                              float* __restrict__ node_out) {
    extern __shared__ char smem[];
    int n0 = blockIdx.x*TILE_M;
    int tid = threadIdx.x;

    auto load_chunk = [&](int ch){
        char* base = smem + (ch%3)*SSTRIDE_G;
        __nv_bfloat16* AH = (__nv_bfloat16*)base;
        __nv_bfloat16* BH = (__nv_bfloat16*)(base + A_BYTES);
        int brs = ch >= 72;
        int kk = (brs ? ch-72 : ch)*32;
        {
            int row = tid >> 2, c16 = tid & 3;
            cpa16(smem_u32(AH + row*PADK + c16*8),
                  g_Ph[brs] + (size_t)(n0+row)*(Rr*Cc) + kk + c16*8);
        }
        int rb = kk >> 8, c0 = kk & 255;
        const __nv_bfloat16* Wh = g_Wt_hi[2+brs] + (size_t)rb*Cc*Cc + c0;
#pragma unroll
        for (int it = 0; it < 2; it++) {
            int i = it*512 + tid; int row = i >> 2, c16 = i & 3;
            cpa16(smem_u32(BH + row*PADK + c16*8), Wh + (size_t)row*Cc + c16*8);
        }
        cpa_commit();
    };

    int lane = tid & 31, wid = tid >> 5;
    int gid = lane >> 2, tig = lane & 3;
    int wm = wid & 3, wn = wid >> 2;

    int a_row = (lane & 15);
    int a_koff = (lane >> 4) << 3;
    int b_row = (lane & 7) + (((lane >> 4) & 1) << 3);
    int b_koff = ((lane >> 3) & 1) << 3;

    float acc[2][8][4];
#pragma unroll
    for (int mt = 0; mt < 2; mt++)
#pragma unroll
        for (int nt = 0; nt < 8; nt++)
#pragma unroll
            for (int q = 0; q < 4; q++) acc[mt][nt][q] = 0.f;

    const int NCH = 144;
    load_chunk(0);
    load_chunk(1);
    for (int ch = 0; ch < NCH; ch++) {
        if (ch + 2 < NCH) { load_chunk(ch+2); cpa_wait2(); }
        else if (ch + 1 < NCH) cpa_wait1();
        else cpa_wait0();
        __syncthreads();
        char* base = smem + (ch%3)*SSTRIDE_G;
        uint32_t aA = smem_u32(base);
        uint32_t aB = smem_u32(base + A_BYTES);
#pragma unroll
        for (int ks = 0; ks < 2; ks++) {
            int kc = ks*16;
            uint32_t ah[2][4];
#pragma unroll
            for (int mt = 0; mt < 2; mt++)
                ldsm4(ah[mt], aA + ((wm*32 + mt*16 + a_row)*PADK + kc + a_koff)*2);
            uint32_t bb[8][2];
#pragma unroll
            for (int ntp = 0; ntp < 4; ntp++) {
                uint32_t r[4];
                ldsm4(r, aB + ((wn*64 + ntp*16 + b_row)*PADK + kc + b_koff)*2);
                bb[2*ntp][0] = r[0]; bb[2*ntp][1] = r[1];
                bb[2*ntp+1][0] = r[2]; bb[2*ntp+1][1] = r[3];
            }
#pragma unroll
            for (int nt = 0; nt < 8; nt++)
#pragma unroll
                for (int mt = 0; mt < 2; mt++)
                    mma16816(acc[mt][nt], ah[mt], bb[nt][0], bb[nt][1]);
        }
        __syncthreads();
    }

    int cbase = wn*64 + 2*tig;
#pragma unroll
    for (int mt = 0; mt < 2; mt++)
#pragma unroll
        for (int h = 0; h < 2; h++) {
            int n = n0 + wm*32 + mt*16 + h*8 + gid;
            float* op = node_out + (size_t)n*Cc + cbase;
            const float* nfp = nf + (size_t)n*Cc + cbase;
#pragma unroll
            for (int nt = 0; nt < 8; nt++) {
                float2 b2 = *(const float2*)(nfp + nt*8);
                float2 w;
                w.x = b2.x + 0.5f*acc[mt][nt][h*2+0];
                w.y = b2.y + 0.5f*acc[mt][nt][h*2+1];
                *(float2*)(op + nt*8) = w;
            }
        }
}

extern "C" void kernel_launch(void* const* d_in, const int* in_sizes, int n_in,
                              void* d_out, int out_size) {
    const int* ei      = (const int*)d_in[0];
    const int* src     = ei;
    const int* dst     = ei + Ee;
    const float* nf    = (const float*)d_in[1];
    const float* ef    = (const float*)d_in[2];
    const int* et_rel  = (const int*)d_in[3];
    const int* et_inv  = (const int*)d_in[4];
    const float* s2r_b = (const float*)d_in[6];
    const float* s2r_a = (const float*)d_in[7];
    const float* o2r_b = (const float*)d_in[8];
    const float* o2r_a = (const float*)d_in[9];
    const float* r2s_b = (const float*)d_in[10];
    const float* r2s_a = (const float*)d_in[11];
    const float* r2s_w = (const float*)d_in[12];
    const float* r2s_bias = (const float*)d_in[13];
    const float* r2o_b = (const float*)d_in[14];
    const float* r2o_a = (const float*)d_in[15];
    const float* r2o_w = (const float*)d_in[16];
    const float* r2o_bias = (const float*)d_in[17];

    float* node_out = (float*)d_out;
    float* rel_out  = node_out + (size_t)Nn*Cc;

    cudaFuncSetAttribute(k_edge, cudaFuncAttributeMaxDynamicSharedMemorySize, SM2_TOTAL);
    cudaFuncSetAttribute(k_g3, cudaFuncAttributeMaxDynamicSharedMemorySize, SM3_TOTAL);

    k_initnf<<<(Nn*Cc)/256, 256>>>(nf);
    k_wtb<<<4*Rr*64, 256>>>(s2r_b, s2r_a, o2r_b, o2r_a, r2s_b, r2s_a, r2o_b, r2o_a);
    k_vb<<<2*Rr, 256>>>(r2s_b, r2s_a, r2s_w, r2o_b, r2o_a, r2o_w);
    k_hist<<<256, 256>>>(src, dst, et_rel, et_inv);
    k_smallscan<<<1, 32>>>();
    k_tilefill<<<NPAIR, 128>>>();
    k_binscatter<<<256, 256>>>(et_rel, et_inv);
    k_scan1<<<2*NCHUNK, 256>>>();
    k_scan2<<<1, 32>>>();
    k_scan3<<<2*NCHUNK, 256>>>();
    k_csrscatter<<<Ee/256, 256>>>(src, dst, et_rel, et_inv);
    k_invdiv<<<Nn/256, 256>>>();

    k_edge<<<TILES2, 512, SM2_TOTAL>>>(src, dst, ef, rel_out, r2s_bias, r2o_bias);
    k_pfill<<<2*NK/8, 256>>>();
    k_g3<<<Nn/TILE_M, 512, SM3_TOTAL>>>(nf, node_out);
}

// round 16
// speedup vs baseline: 1.8256x; 1.0415x over previous
// R16: third submission of the 2-CTA/SM 64x256-tile kernel. R14 and R15 both
// failed at GB300 container acquisition ("container failed twice") — an infra
// error raised before kernel compile/run, not a kernel verdict. Source is
// functionally identical to R14/R15.
#include <cuda_runtime.h>
#include <cuda_bf16.h>
#include <math.h>
#include <stdint.h>

#define Nn 16384
#define Ee 262144
#define Cc 256
#define Rr 9
#define Bb 4
#define NK (Nn*Rr)
#define NCHUNK (NK/1024)
#define TILE_M 64
#define NPAIR (Rr*Rr)                 /* 81 */
#define TILES2 (Ee/TILE_M + NPAIR)    /* 4177 */

#define PADK 40                       /* padded bf16 cols per 32-col chunk row */

#define A_BYTES  (64*PADK*2)          /* 5120 */
#define B_BYTES  (256*PADK*2)         /* 20480 */

/* edge kernel smem: AH+BH per stage, 2 stages */
#define SM2_ES   0
#define SM2_GSS  256
#define SM2_GSD  512
#define SM2_BUF  1024
#define SSTRIDE_E (A_BYTES + B_BYTES)      /* 25600 */
#define SM2_TOTAL (SM2_BUF + 2*SSTRIDE_E)  /* 52224 */

/* g3 kernel smem */
#define SSTRIDE_G (A_BYTES + B_BYTES)      /* 25600 */
#define SM3_TOTAL (2*SSTRIDE_G)            /* 51200 */

// ---------------- static scratch ----------------
__device__ __align__(16) __nv_bfloat16 g_Wt_hi[4][Rr*Cc*Cc]; // transposed [n][k]
__device__ __align__(16) __nv_bfloat16 g_nf_hi[(size_t)Nn*Cc];
__device__ __align__(16) __nv_bfloat16 g_relb[(size_t)Ee*Cc]; // bf16 mirror of rel_emb
__device__ float g_v[2][Rr*Cc];
__device__ float g_scores[2][Ee];
__device__ int   g_counts[2][NK];
__device__ int   g_rowptr[2][NK+1];
__device__ int   g_cursor[2][NK];
__device__ int   g_elist[2][Ee];
__device__ int   g_partials[2][NCHUNK];
__device__ __align__(16) __nv_bfloat16 g_Ph[2][(size_t)NK*Cc];
__device__ float g_invdiv[2][Nn];
__device__ int   g_pairCount[NPAIR];
__device__ int   g_pairStart[NPAIR+1];
__device__ int   g_tileStart2[NPAIR+1];
__device__ int   g_pairCursor[NPAIR];
__device__ int   g_perm2[Ee];
__device__ int4  g_tile[TILES2];

// ---------------- helpers ----------------
__device__ __forceinline__ uint32_t smem_u32(const void* p){
    return (uint32_t)__cvta_generic_to_shared((void*)p);
}
__device__ __forceinline__ void cpa16(uint32_t d, const void* s){
    asm volatile("cp.async.cg.shared.global [%0], [%1], 16;" :: "r"(d), "l"(s) : "memory");
}
__device__ __forceinline__ void cpa_commit(){
    asm volatile("cp.async.commit_group;" ::: "memory");
}
__device__ __forceinline__ void cpa_wait1(){
    asm volatile("cp.async.wait_group 1;" ::: "memory");
}
__device__ __forceinline__ void cpa_wait0(){
    asm volatile("cp.async.wait_group 0;" ::: "memory");
}
__device__ __forceinline__ void mma16816(float* c, const uint32_t* a, uint32_t b0, uint32_t b1){
    asm volatile("mma.sync.aligned.m16n8k16.row.col.f32.bf16.bf16.f32 "
        "{%0,%1,%2,%3}, {%4,%5,%6,%7}, {%8,%9}, {%0,%1,%2,%3};"
        : "+f"(c[0]), "+f"(c[1]), "+f"(c[2]), "+f"(c[3])
        : "r"(a[0]), "r"(a[1]), "r"(a[2]), "r"(a[3]), "r"(b0), "r"(b1));
}
__device__ __forceinline__ void ldsm4(uint32_t* r, uint32_t addr){
    asm volatile("ldmatrix.sync.aligned.m8n8.x4.shared.b16 {%0,%1,%2,%3}, [%4];"
        : "=r"(r[0]), "=r"(r[1]), "=r"(r[2]), "=r"(r[3]) : "r"(addr));
}

// ---------------- setup kernels ----------------
__global__ void k_initnf(const float* __restrict__ nf) {
    int i = blockIdx.x*256 + threadIdx.x;
    g_nf_hi[i] = __float2bfloat16(nf[i]);
    if (i < 2*NK) ((int*)g_counts)[i] = 0;
    if (i < NPAIR) g_pairCount[i] = 0;
}

__global__ void k_wtb(const float* b0, const float* a0, const float* b1, const float* a1,
                      const float* b2, const float* a2, const float* b3, const float* a3) {
    __shared__ float t[32][33];
    int bid = blockIdx.x;
    int br = bid / (Rr*64);
    int rem = bid % (Rr*64);
    int r = rem / 64, tile = rem % 64;
    int ti = (tile/8)*32, tj = (tile%8)*32;
    int lx = threadIdx.x & 31, ly = threadIdx.x >> 5;
    const float* bas = (br==0)?b0:(br==1)?b1:(br==2)?b2:b3;
    const float* att = (br==0)?a0:(br==1)?a1:(br==2)?a2:a3;
#pragma unroll
    for (int s = 0; s < 32; s += 8) {
        int i = ti+ly+s, j = tj+lx;
        float w = 0.f;
#pragma unroll
        for (int b = 0; b < Bb; b++) w += att[r*Bb+b]*bas[(b*Cc+i)*Cc + j];
        t[ly+s][lx] = w;
    }
    __syncthreads();
    __nv_bfloat16* Wh = g_Wt_hi[br] + r*Cc*Cc;
#pragma unroll
    for (int s = 0; s < 32; s += 8)
        Wh[(tj+ly+s)*Cc + ti+lx] = __float2bfloat16(t[lx][ly+s]);
}

__global__ void k_vb(const float* r2s_bas, const float* r2s_att, const float* r2s_aw,
                     const float* r2o_bas, const float* r2o_att, const float* r2o_aw) {
    int br = blockIdx.x / Rr, r = blockIdx.x % Rr;
    const float* bas = br ? r2o_bas : r2s_bas;
    const float* att = br ? r2o_att : r2s_att;
    const float* aw  = br ? r2o_aw  : r2s_aw;
    int i = threadIdx.x;
    float s = 0.f;
    for (int j = 0; j < Cc; j++) {
        float w = 0.f;
#pragma unroll
        for (int b = 0; b < Bb; b++) w += att[r*Bb+b]*bas[(b*Cc+i)*Cc + j];
        s += w*aw[r*Cc+j];
    }
    g_v[br][r*Cc+i] = s;
}

__global__ void k_hist(const int* src, const int* dst, const int* et_rel, const int* et_inv) {
    __shared__ int h[NPAIR];
    int tid = threadIdx.x;
    if (tid < NPAIR) h[tid] = 0;
    __syncthreads();
#pragma unroll
    for (int u = 0; u < 4; u++) {
        int e = blockIdx.x*1024 + u*256 + tid;
        int r1 = et_rel[e], r2 = et_inv[e];
        atomicAdd(&h[r1*Rr + r2], 1);
        atomicAdd(&g_counts[0][src[e]*Rr + r2], 1);
        atomicAdd(&g_counts[1][dst[e]*Rr + r1], 1);
    }
    __syncthreads();
    if (tid < NPAIR) atomicAdd(&g_pairCount[tid], h[tid]);
}

__global__ void k_smallscan() {
    if (threadIdx.x == 0) {
        int s = 0, t = 0;
        for (int p = 0; p < NPAIR; p++) {
            g_pairStart[p] = s; g_tileStart2[p] = t; g_pairCursor[p] = s;
            int c = g_pairCount[p];
            s += c; t += (c + TILE_M-1)/TILE_M;
        }
        g_pairStart[NPAIR] = s; g_tileStart2[NPAIR] = t;
    }
}

__global__ void k_tilefill() {
    int p = blockIdx.x;
    int r1 = p / Rr, r2 = p % Rr;
    int s0 = g_pairStart[p], s1 = g_pairStart[p+1];
    int t0 = g_tileStart2[p];
    int nt = (s1 - s0 + TILE_M-1)/TILE_M;
    for (int i = threadIdx.x; i < nt; i += blockDim.x)
        g_tile[t0+i] = make_int4(r1, r2, s0 + i*TILE_M, s1);
}

__global__ void k_binscatter(const int* et_rel, const int* et_inv) {
    __shared__ int h[NPAIR], base[NPAIR], loc[NPAIR];
    int tid = threadIdx.x;
    if (tid < NPAIR) { h[tid] = 0; loc[tid] = 0; }
    __syncthreads();
    int es[4], ps[4];
#pragma unroll
    for (int u = 0; u < 4; u++) {
        int e = blockIdx.x*1024 + u*256 + tid;
        es[u] = e; ps[u] = et_rel[e]*Rr + et_inv[e];
        atomicAdd(&h[ps[u]], 1);
    }
    __syncthreads();
    if (tid < NPAIR) base[tid] = atomicAdd(&g_pairCursor[tid], h[tid]);
    __syncthreads();
#pragma unroll
    for (int u = 0; u < 4; u++) {
        int p = base[ps[u]] + atomicAdd(&loc[ps[u]], 1);
        g_perm2[p] = es[u];
    }
}

__global__ void k_scan1() {
    int br = blockIdx.x / NCHUNK, ch = blockIdx.x % NCHUNK;
    int tid = threadIdx.x;
    int basei = ch*1024 + tid*4;
    int v[4]; int t = 0;
#pragma unroll
    for (int i = 0; i < 4; i++) { v[i] = g_counts[br][basei+i]; t += v[i]; }
    __shared__ int s[256];
    s[tid] = t; __syncthreads();
    for (int off = 1; off < 256; off <<= 1) {
        int x = (tid >= off) ? s[tid-off] : 0;
        __syncthreads();
        s[tid] += x;
        __syncthreads();
    }
    int excl = s[tid] - t;
#pragma unroll
    for (int i = 0; i < 4; i++) { g_rowptr[br][basei+i] = excl; excl += v[i]; }
    if (tid == 255) g_partials[br][ch] = s[255];
}

__global__ void k_scan2() {
    int br = threadIdx.x;
    if (br < 2) {
        int run = 0;
        for (int c = 0; c < NCHUNK; c++) { int p = g_partials[br][c]; g_partials[br][c] = run; run += p; }
        g_rowptr[br][NK] = run;
    }
}

__global__ void k_scan3() {
    int br = blockIdx.x / NCHUNK, ch = blockIdx.x % NCHUNK;
    int add = g_partials[br][ch];
    int basei = ch*1024 + threadIdx.x*4;
#pragma unroll
    for (int i = 0; i < 4; i++) {
        int p = g_rowptr[br][basei+i] + add;
        g_rowptr[br][basei+i] = p;
        g_cursor[br][basei+i] = p;
    }
}

__global__ void k_csrscatter(const int* src, const int* dst, const int* et_rel, const int* et_inv) {
    int e = blockIdx.x*256 + threadIdx.x;
    int k0 = src[e]*Rr + et_inv[e];
    g_elist[0][atomicAdd(&g_cursor[0][k0], 1)] = e;
    int k1 = dst[e]*Rr + et_rel[e];
    g_elist[1][atomicAdd(&g_cursor[1][k1], 1)] = e;
}

__global__ void k_invdiv() {
    int n = blockIdx.x*256 + threadIdx.x;
#pragma unroll
    for (int br = 0; br < 2; br++) {
        int c = 0;
        for (int r = 0; r < Rr; r++)
            if (g_rowptr[br][n*Rr+r+1] > g_rowptr[br][n*Rr+r]) c++;
        g_invdiv[br][n] = c ? 1.f/(float)c : 1.f;
    }
}

// ---------------- fused pair-binned edge GEMM + score ----------------
// 64x256 tile, 256 threads, 2 CTAs/SM; rel = ef + 0.5*([nf[src],nf[dst]] @ [W0;W1])
__global__ void __launch_bounds__(256,2) k_edge(const int* __restrict__ src,
        const int* __restrict__ dst, const float* __restrict__ ef,
        float* __restrict__ rel_out,
        const float* __restrict__ bias_sub, const float* __restrict__ bias_obj) {
    extern __shared__ char smem[];
    int bx = blockIdx.x;
    if (bx >= g_tileStart2[NPAIR]) return;
    int4 tp = g_tile[bx];
    int r1 = tp.x, r2 = tp.y, row0 = tp.z, rowEnd = tp.w;

    int tid = threadIdx.x;
    int* es  = (int*)(smem + SM2_ES);
    int* gsS = (int*)(smem + SM2_GSS);
    int* gsD = (int*)(smem + SM2_GSD);
    if (tid < 64) {
        int row = row0 + tid;
        if (row < rowEnd) { int e = g_perm2[row]; es[tid] = e; gsS[tid] = src[e]; gsD[tid] = dst[e]; }
        else { es[tid] = -1; gsS[tid] = 0; gsD[tid] = 0; }
    }
    __syncthreads();

    const __nv_bfloat16* __restrict__ W1h = g_Wt_hi[0] + (size_t)r1*Cc*Cc;
    const __nv_bfloat16* __restrict__ W2h = g_Wt_hi[1] + (size_t)r2*Cc*Cc;

    auto load_chunk = [&](int ch, int st){
        char* base = smem + SM2_BUF + st*SSTRIDE_E;
        __nv_bfloat16* AH = (__nv_bfloat16*)base;
        __nv_bfloat16* BH = (__nv_bfloat16*)(base + A_BYTES);
        int srcside = ch < 8;
        int k0 = (ch & 7)*32;
        {
            int row = tid >> 2, c16 = tid & 3;
            int node = srcside ? gsS[row] : gsD[row];
            cpa16(smem_u32(AH + row*PADK + c16*8), g_nf_hi + (size_t)node*Cc + k0 + c16*8);
        }
        const __nv_bfloat16* Wh = srcside ? W1h : W2h;
#pragma unroll
        for (int it = 0; it < 4; it++) {
            int i = it*256 + tid; int row = i >> 2, c16 = i & 3;
            cpa16(smem_u32(BH + row*PADK + c16*8), Wh + (size_t)row*Cc + k0 + c16*8);
        }
        cpa_commit();
    };

    int lane = tid & 31, wid = tid >> 5;
    int gid = lane >> 2, tig = lane & 3;
    int wm = wid & 1, wn = wid >> 1;

    int a_row = (lane & 15);
    int a_koff = (lane >> 4) << 3;
    int b_row = (lane & 7) + (((lane >> 4) & 1) << 3);
    int b_koff = ((lane >> 3) & 1) << 3;

    float acc[2][8][4];
#pragma unroll
    for (int mt = 0; mt < 2; mt++)
#pragma unroll
        for (int nt = 0; nt < 8; nt++)
#pragma unroll
            for (int q = 0; q < 4; q++) acc[mt][nt][q] = 0.f;

    load_chunk(0, 0);
    for (int ch = 0; ch < 16; ch++) {
        if (ch < 15) { load_chunk(ch+1, (ch+1)&1); cpa_wait1(); }
        else cpa_wait0();
        __syncthreads();
        char* base = smem + SM2_BUF + (ch&1)*SSTRIDE_E;
        uint32_t aA = smem_u32(base);
        uint32_t aB = smem_u32(base + A_BYTES);
#pragma unroll
        for (int ks = 0; ks < 2; ks++) {
            int kc = ks*16;
            uint32_t ah[2][4];
#pragma unroll
            for (int mt = 0; mt < 2; mt++)
                ldsm4(ah[mt], aA + ((wm*32 + mt*16 + a_row)*PADK + kc + a_koff)*2);
            uint32_t bb[8][2];
#pragma unroll
            for (int ntp = 0; ntp < 4; ntp++) {
                uint32_t r[4];
                ldsm4(r, aB + ((wn*64 + ntp*16 + b_row)*PADK + kc + b_koff)*2);
                bb[2*ntp][0] = r[0]; bb[2*ntp][1] = r[1];
                bb[2*ntp+1][0] = r[2]; bb[2*ntp+1][1] = r[3];
            }
#pragma unroll
            for (int nt = 0; nt < 8; nt++)
#pragma unroll
                for (int mt = 0; mt < 2; mt++)
                    mma16816(acc[mt][nt], ah[mt], bb[nt][0], bb[nt][1]);
        }
        __syncthreads();
    }

    // epilogue: rel write (fp32 + bf16 mirror) + fused scores
    float* sc0 = (float*)(smem + SM2_BUF);
    float* sc1 = sc0 + 64;
    if (tid < 64) { sc0[tid] = 0.f; sc1[tid] = 0.f; }
    __syncthreads();

    const float* vs = g_v[0] + r2*Cc;
    const float* vo = g_v[1] + r1*Cc;
    int cbase = wn*64 + 2*tig;
#pragma unroll
    for (int mt = 0; mt < 2; mt++)
#pragma unroll
        for (int h = 0; h < 2; h++) {
            int row = wm*32 + mt*16 + h*8 + gid;
            int e = es[row];
            float s0 = 0.f, s1 = 0.f;
            if (e >= 0) {
                float* op = rel_out + (size_t)e*Cc + cbase;
                const float* efp = ef + (size_t)e*Cc + cbase;
                __nv_bfloat16* rb = g_relb + (size_t)e*Cc + cbase;
#pragma unroll
                for (int nt = 0; nt < 8; nt++) {
                    int c = cbase + nt*8;
                    float2 e2 = *(const float2*)(efp + nt*8);
                    float wx = e2.x + 0.5f*acc[mt][nt][h*2+0];
                    float wy = e2.y + 0.5f*acc[mt][nt][h*2+1];
                    *(float2*)(op + nt*8) = make_float2(wx, wy);
                    *(__nv_bfloat162*)(rb + nt*8) = __floats2bfloat162_rn(wx, wy);
                    s0 += wx*vs[c] + wy*vs[c+1];
                    s1 += wx*vo[c] + wy*vo[c+1];
                }
            }
            s0 += __shfl_xor_sync(0xffffffffu, s0, 1);
            s0 += __shfl_xor_sync(0xffffffffu, s0, 2);
            s1 += __shfl_xor_sync(0xffffffffu, s1, 1);
            s1 += __shfl_xor_sync(0xffffffffu, s1, 2);
            if (tig == 0 && e >= 0) {
                atomicAdd(&sc0[row], s0);
                atomicAdd(&sc1[row], s1);
            }
        }
    __syncthreads();
    if (tid < 64) {
        int e = es[tid];
        if (e >= 0) {
            float a = sc0[tid] + bias_sub[r2]; a = (a >= 0.f) ? a : 0.01f*a;
            float b = sc1[tid] + bias_obj[r1]; b = (b >= 0.f) ? b : 0.01f*b;
            g_scores[0][e] = a;
            g_scores[1][e] = b;
        }
    }
}

// P fill (both branches): invdiv-scaled softmax-weighted sums from bf16 rel, single pass
__global__ void k_pfill() {
    int w = blockIdx.x*8 + (threadIdx.x >> 5);
    int lane = threadIdx.x & 31;
    int br = (w >= NK) ? 1 : 0;
    int key = w - br*NK;
    if (w >= 2*NK) return;
    int lo = g_rowptr[br][key], hi = g_rowptr[br][key+1];
    float2 acc[4];
#pragma unroll
    for (int j = 0; j < 4; j++) acc[j] = make_float2(0.f, 0.f);
    if (lo < hi) {
        float den = 0.f;
        for (int p = lo; p < hi; p++) {
            int e = g_elist[br][p];
            float wt = expf(g_scores[br][e]);
            den += wt;
            const __nv_bfloat162* x = (const __nv_bfloat162*)(g_relb + (size_t)e*Cc);
#pragma unroll
            for (int j = 0; j < 4; j++) {
                __nv_bfloat162 v = x[lane + 32*j];
                acc[j].x += wt*__low2float(v);
                acc[j].y += wt*__high2float(v);
            }
        }
        float inv = g_invdiv[br][key/Rr]/den;
#pragma unroll
        for (int j = 0; j < 4; j++) { acc[j].x *= inv; acc[j].y *= inv; }
    }
    __nv_bfloat162* Ph = (__nv_bfloat162*)(g_Ph[br] + (size_t)key*Cc);
#pragma unroll
    for (int j = 0; j < 4; j++) Ph[lane + 32*j] = __floats2bfloat162_rn(acc[j].x, acc[j].y);
}

// ---------------- fused agg GEMM: out = nf + 0.5*([P0,P1] @ [W2;W3])  (K=4608) ----------------
// 64x256 tile, 256 threads, 2 CTAs/SM
__global__ void __launch_bounds__(256,2) k_g3(const float* __restrict__ nf,
                                              float* __restrict__ node_out) {
    extern __shared__ char smem[];
    int n0 = blockIdx.x*TILE_M;
    int tid = threadIdx.x;

    auto load_chunk = [&](int ch, int st){
        char* base = smem + st*SSTRIDE_G;
        __nv_bfloat16* AH = (__nv_bfloat16*)base;
        __nv_bfloat16* BH = (__nv_bfloat16*)(base + A_BYTES);
        int brs = ch >= 72;
        int kk = (brs ? ch-72 : ch)*32;
        {
            int row = tid >> 2, c16 = tid & 3;
            cpa16(smem_u32(AH + row*PADK + c16*8),
                  g_Ph[brs] + (size_t)(n0+row)*(Rr*Cc) + kk + c16*8);
        }
        int rb = kk >> 8, c0 = kk & 255;
        const __nv_bfloat16* Wh = g_Wt_hi[2+brs] + (size_t)rb*Cc*Cc + c0;
#pragma unroll
        for (int it = 0; it < 4; it++) {
            int i = it*256 + tid; int row = i >> 2, c16 = i & 3;
            cpa16(smem_u32(BH + row*PADK + c16*8), Wh + (size_t)row*Cc + c16*8);
        }
        cpa_commit();
    };

    int lane = tid & 31, wid = tid >> 5;
    int gid = lane >> 2, tig = lane & 3;
    int wm = wid & 1, wn = wid >> 1;

    int a_row = (lane & 15);
    int a_koff = (lane >> 4) << 3;
    int b_row = (lane & 7) + (((lane >> 4) & 1) << 3);
    int b_koff = ((lane >> 3) & 1) << 3;

    float acc[2][8][4];
#pragma unroll
    for (int mt = 0; mt < 2; mt++)
#pragma unroll
        for (int nt = 0; nt < 8; nt++)
#pragma unroll
            for (int q = 0; q < 4; q++) acc[mt][nt][q] = 0.f;

    const int NCH = 144;
    load_chunk(0, 0);
    for (int ch = 0; ch < NCH; ch++) {
        if (ch < NCH-1) { load_chunk(ch+1, (ch+1)&1); cpa_wait1(); }
        else cpa_wait0();
        __syncthreads();
        char* base = smem + (ch&1)*SSTRIDE_G;
        uint32_t aA = smem_u32(base);
        uint32_t aB = smem_u32(base + A_BYTES);
#pragma unroll
        for (int ks = 0; ks < 2; ks++) {
            int kc = ks*16;
            uint32_t ah[2][4];
#pragma unroll
            for (int mt = 0; mt < 2; mt++)
                ldsm4(ah[mt], aA + ((wm*32 + mt*16 + a_row)*PADK + kc + a_koff)*2);
            uint32_t bb[8][2];
#pragma unroll
            for (int ntp = 0; ntp < 4; ntp++) {
                uint32_t r[4];
                ldsm4(r, aB + ((wn*64 + ntp*16 + b_row)*PADK + kc + b_koff)*2);
                bb[2*ntp][0] = r[0]; bb[2*ntp][1] = r[1];
                bb[2*ntp+1][0] = r[2]; bb[2*ntp+1][1] = r[3];
            }
#pragma unroll
            for (int nt = 0; nt < 8; nt++)
#pragma unroll
                for (int mt = 0; mt < 2; mt++)
                    mma16816(acc[mt][nt], ah[mt], bb[nt][0], bb[nt][1]);
        }
        __syncthreads();
    }

    int cbase = wn*64 + 2*tig;
#pragma unroll
    for (int mt = 0; mt < 2; mt++)
#pragma unroll
        for (int h = 0; h < 2; h++) {
            int n = n0 + wm*32 + mt*16 + h*8 + gid;
            float* op = node_out + (size_t)n*Cc + cbase;
            const float* nfp = nf + (size_t)n*Cc + cbase;
#pragma unroll
            for (int nt = 0; nt < 8; nt++) {
                float2 b2 = *(const float2*)(nfp + nt*8);
                float2 w;
                w.x = b2.x + 0.5f*acc[mt][nt][h*2+0];
                w.y = b2.y + 0.5f*acc[mt][nt][h*2+1];
                *(float2*)(op + nt*8) = w;
            }
        }
}

extern "C" void kernel_launch(void* const* d_in, const int* in_sizes, int n_in,
                              void* d_out, int out_size) {
    const int* ei      = (const int*)d_in[0];
    const int* src     = ei;
    const int* dst     = ei + Ee;
    const float* nf    = (const float*)d_in[1];
    const float* ef    = (const float*)d_in[2];
    const int* et_rel  = (const int*)d_in[3];
    const int* et_inv  = (const int*)d_in[4];
    const float* s2r_b = (const float*)d_in[6];
    const float* s2r_a = (const float*)d_in[7];
    const float* o2r_b = (const float*)d_in[8];
    const float* o2r_a = (const float*)d_in[9];
    const float* r2s_b = (const float*)d_in[10];
    const float* r2s_a = (const float*)d_in[11];
    const float* r2s_w = (const float*)d_in[12];
    const float* r2s_bias = (const float*)d_in[13];
    const float* r2o_b = (const float*)d_in[14];
    const float* r2o_a = (const float*)d_in[15];
    const float* r2o_w = (const float*)d_in[16];
    const float* r2o_bias = (const float*)d_in[17];

    float* node_out = (float*)d_out;
    float* rel_out  = node_out + (size_t)Nn*Cc;

    cudaFuncSetAttribute(k_edge, cudaFuncAttributeMaxDynamicSharedMemorySize, SM2_TOTAL);
    cudaFuncSetAttribute(k_g3, cudaFuncAttributeMaxDynamicSharedMemorySize, SM3_TOTAL);

    k_initnf<<<(Nn*Cc)/256, 256>>>(nf);
    k_wtb<<<4*Rr*64, 256>>>(s2r_b, s2r_a, o2r_b, o2r_a, r2s_b, r2s_a, r2o_b, r2o_a);
    k_vb<<<2*Rr, 256>>>(r2s_b, r2s_a, r2s_w, r2o_b, r2o_a, r2o_w);
    k_hist<<<256, 256>>>(src, dst, et_rel, et_inv);
    k_smallscan<<<1, 32>>>();
    k_tilefill<<<NPAIR, 128>>>();
    k_binscatter<<<256, 256>>>(et_rel, et_inv);
    k_scan1<<<2*NCHUNK, 256>>>();
    k_scan2<<<1, 32>>>();
    k_scan3<<<2*NCHUNK, 256>>>();
    k_csrscatter<<<Ee/256, 256>>>(src, dst, et_rel, et_inv);
    k_invdiv<<<Nn/256, 256>>>();

    k_edge<<<TILES2, 256, SM2_TOTAL>>>(src, dst, ef, rel_out, r2s_bias, r2o_bias);
    k_pfill<<<2*NK/8, 256>>>();
    k_g3<<<Nn/TILE_M, 256, SM3_TOTAL>>>(nf, node_out);
}

// round 17
// speedup vs baseline: 1.9233x; 1.0535x over previous
// R17: K-chunk 64 (half the chunk-boundary overhead), merged scatter kernel.
#include <cuda_runtime.h>
#include <cuda_bf16.h>
#include <math.h>
#include <stdint.h>

#define Nn 16384
#define Ee 262144
#define Cc 256
#define Rr 9
#define Bb 4
#define NK (Nn*Rr)
#define NCHUNK (NK/1024)
#define TILE_M 64
#define NPAIR (Rr*Rr)                 /* 81 */
#define TILES2 (Ee/TILE_M + NPAIR)    /* 4177 */

#define PADK 72                       /* padded bf16 cols per 64-col chunk row */

#define A_BYTES  (64*PADK*2)          /* 9216 */
#define B_BYTES  (256*PADK*2)         /* 36864 */

/* edge kernel smem: AH+BH per stage, 2 stages */
#define SM2_ES   0
#define SM2_GSS  256
#define SM2_GSD  512
#define SM2_BUF  1024
#define SSTRIDE_E (A_BYTES + B_BYTES)      /* 46080 */
#define SM2_TOTAL (SM2_BUF + 2*SSTRIDE_E)  /* 93184 */

/* g3 kernel smem */
#define SSTRIDE_G (A_BYTES + B_BYTES)      /* 46080 */
#define SM3_TOTAL (2*SSTRIDE_G)            /* 92160 */

// ---------------- static scratch ----------------
__device__ __align__(16) __nv_bfloat16 g_Wt_hi[4][Rr*Cc*Cc]; // transposed [n][k]
__device__ __align__(16) __nv_bfloat16 g_nf_hi[(size_t)Nn*Cc];
__device__ __align__(16) __nv_bfloat16 g_relb[(size_t)Ee*Cc]; // bf16 mirror of rel_emb
__device__ float g_v[2][Rr*Cc];
__device__ float g_scores[2][Ee];
__device__ int   g_counts[2][NK];
__device__ int   g_rowptr[2][NK+1];
__device__ int   g_cursor[2][NK];
__device__ int   g_elist[2][Ee];
__device__ int   g_partials[2][NCHUNK];
__device__ __align__(16) __nv_bfloat16 g_Ph[2][(size_t)NK*Cc];
__device__ float g_invdiv[2][Nn];
__device__ int   g_pairCount[NPAIR];
__device__ int   g_pairStart[NPAIR+1];
__device__ int   g_tileStart2[NPAIR+1];
__device__ int   g_pairCursor[NPAIR];
__device__ int   g_perm2[Ee];
__device__ int4  g_tile[TILES2];

// ---------------- helpers ----------------
__device__ __forceinline__ uint32_t smem_u32(const void* p){
    return (uint32_t)__cvta_generic_to_shared((void*)p);
}
__device__ __forceinline__ void cpa16(uint32_t d, const void* s){
    asm volatile("cp.async.cg.shared.global [%0], [%1], 16;" :: "r"(d), "l"(s) : "memory");
}
__device__ __forceinline__ void cpa_commit(){
    asm volatile("cp.async.commit_group;" ::: "memory");
}
__device__ __forceinline__ void cpa_wait1(){
    asm volatile("cp.async.wait_group 1;" ::: "memory");
}
__device__ __forceinline__ void cpa_wait0(){
    asm volatile("cp.async.wait_group 0;" ::: "memory");
}
__device__ __forceinline__ void mma16816(float* c, const uint32_t* a, uint32_t b0, uint32_t b1){
    asm volatile("mma.sync.aligned.m16n8k16.row.col.f32.bf16.bf16.f32 "
        "{%0,%1,%2,%3}, {%4,%5,%6,%7}, {%8,%9}, {%0,%1,%2,%3};"
        : "+f"(c[0]), "+f"(c[1]), "+f"(c[2]), "+f"(c[3])
        : "r"(a[0]), "r"(a[1]), "r"(a[2]), "r"(a[3]), "r"(b0), "r"(b1));
}
__device__ __forceinline__ void ldsm4(uint32_t* r, uint32_t addr){
    asm volatile("ldmatrix.sync.aligned.m8n8.x4.shared.b16 {%0,%1,%2,%3}, [%4];"
        : "=r"(r[0]), "=r"(r[1]), "=r"(r[2]), "=r"(r[3]) : "r"(addr));
}

// ---------------- setup kernels ----------------
__global__ void k_initnf(const float* __restrict__ nf) {
    int i = blockIdx.x*256 + threadIdx.x;
    g_nf_hi[i] = __float2bfloat16(nf[i]);
    if (i < 2*NK) ((int*)g_counts)[i] = 0;
    if (i < NPAIR) g_pairCount[i] = 0;
}

__global__ void k_wtb(const float* b0, const float* a0, const float* b1, const float* a1,
                      const float* b2, const float* a2, const float* b3, const float* a3) {
    __shared__ float t[32][33];
    int bid = blockIdx.x;
    int br = bid / (Rr*64);
    int rem = bid % (Rr*64);
    int r = rem / 64, tile = rem % 64;
    int ti = (tile/8)*32, tj = (tile%8)*32;
    int lx = threadIdx.x & 31, ly = threadIdx.x >> 5;
    const float* bas = (br==0)?b0:(br==1)?b1:(br==2)?b2:b3;
    const float* att = (br==0)?a0:(br==1)?a1:(br==2)?a2:a3;
#pragma unroll
    for (int s = 0; s < 32; s += 8) {
        int i = ti+ly+s, j = tj+lx;
        float w = 0.f;
#pragma unroll
        for (int b = 0; b < Bb; b++) w += att[r*Bb+b]*bas[(b*Cc+i)*Cc + j];
        t[ly+s][lx] = w;
    }
    __syncthreads();
    __nv_bfloat16* Wh = g_Wt_hi[br] + r*Cc*Cc;
#pragma unroll
    for (int s = 0; s < 32; s += 8)
        Wh[(tj+ly+s)*Cc + ti+lx] = __float2bfloat16(t[lx][ly+s]);
}

__global__ void k_vb(const float* r2s_bas, const float* r2s_att, const float* r2s_aw,
                     const float* r2o_bas, const float* r2o_att, const float* r2o_aw) {
    int br = blockIdx.x / Rr, r = blockIdx.x % Rr;
    const float* bas = br ? r2o_bas : r2s_bas;
    const float* att = br ? r2o_att : r2s_att;
    const float* aw  = br ? r2o_aw  : r2s_aw;
    int i = threadIdx.x;
    float s = 0.f;
    for (int j = 0; j < Cc; j++) {
        float w = 0.f;
#pragma unroll
        for (int b = 0; b < Bb; b++) w += att[r*Bb+b]*bas[(b*Cc+i)*Cc + j];
        s += w*aw[r*Cc+j];
    }
    g_v[br][r*Cc+i] = s;
}

__global__ void k_hist(const int* src, const int* dst, const int* et_rel, const int* et_inv) {
    __shared__ int h[NPAIR];
    int tid = threadIdx.x;
    if (tid < NPAIR) h[tid] = 0;
    __syncthreads();
#pragma unroll
    for (int u = 0; u < 4; u++) {
        int e = blockIdx.x*1024 + u*256 + tid;
        int r1 = et_rel[e], r2 = et_inv[e];
        atomicAdd(&h[r1*Rr + r2], 1);
        atomicAdd(&g_counts[0][src[e]*Rr + r2], 1);
        atomicAdd(&g_counts[1][dst[e]*Rr + r1], 1);
    }
    __syncthreads();
    if (tid < NPAIR) atomicAdd(&g_pairCount[tid], h[tid]);
}

__global__ void k_smallscan() {
    if (threadIdx.x == 0) {
        int s = 0, t = 0;
        for (int p = 0; p < NPAIR; p++) {
            g_pairStart[p] = s; g_tileStart2[p] = t; g_pairCursor[p] = s;
            int c = g_pairCount[p];
            s += c; t += (c + TILE_M-1)/TILE_M;
        }
        g_pairStart[NPAIR] = s; g_tileStart2[NPAIR] = t;
    }
}

__global__ void k_tilefill() {
    int p = blockIdx.x;
    int r1 = p / Rr, r2 = p % Rr;
    int s0 = g_pairStart[p], s1 = g_pairStart[p+1];
    int t0 = g_tileStart2[p];
    int nt = (s1 - s0 + TILE_M-1)/TILE_M;
    for (int i = threadIdx.x; i < nt; i += blockDim.x)
        g_tile[t0+i] = make_int4(r1, r2, s0 + i*TILE_M, s1);
}

__global__ void k_scan1() {
    int br = blockIdx.x / NCHUNK, ch = blockIdx.x % NCHUNK;
    int tid = threadIdx.x;
    int basei = ch*1024 + tid*4;
    int v[4]; int t = 0;
#pragma unroll
    for (int i = 0; i < 4; i++) { v[i] = g_counts[br][basei+i]; t += v[i]; }
    __shared__ int s[256];
    s[tid] = t; __syncthreads();
    for (int off = 1; off < 256; off <<= 1) {
        int x = (tid >= off) ? s[tid-off] : 0;
        __syncthreads();
        s[tid] += x;
        __syncthreads();
    }
    int excl = s[tid] - t;
#pragma unroll
    for (int i = 0; i < 4; i++) { g_rowptr[br][basei+i] = excl; excl += v[i]; }
    if (tid == 255) g_partials[br][ch] = s[255];
}

__global__ void k_scan2() {
    int br = threadIdx.x;
    if (br < 2) {
        int run = 0;
        for (int c = 0; c < NCHUNK; c++) { int p = g_partials[br][c]; g_partials[br][c] = run; run += p; }
        g_rowptr[br][NK] = run;
    }
}

__global__ void k_scan3() {
    int br = blockIdx.x / NCHUNK, ch = blockIdx.x % NCHUNK;
    int add = g_partials[br][ch];
    int basei = ch*1024 + threadIdx.x*4;
#pragma unroll
    for (int i = 0; i < 4; i++) {
        int p = g_rowptr[br][basei+i] + add;
        g_rowptr[br][basei+i] = p;
        g_cursor[br][basei+i] = p;
    }
}

// merged: pair-binned perm2 scatter + per-(node,rel) CSR elist scatter
__global__ void k_scatter(const int* src, const int* dst, const int* et_rel, const int* et_inv) {
    __shared__ int h[NPAIR], base[NPAIR], loc[NPAIR];
    int tid = threadIdx.x;
    if (tid < NPAIR) { h[tid] = 0; loc[tid] = 0; }
    __syncthreads();
    int es[4], ps[4];
#pragma unroll
    for (int u = 0; u < 4; u++) {
        int e = blockIdx.x*1024 + u*256 + tid;
        es[u] = e; ps[u] = et_rel[e]*Rr + et_inv[e];
        atomicAdd(&h[ps[u]], 1);
    }
    __syncthreads();
    if (tid < NPAIR) base[tid] = atomicAdd(&g_pairCursor[tid], h[tid]);
    __syncthreads();
#pragma unroll
    for (int u = 0; u < 4; u++) {
        int e = es[u];
        int p = base[ps[u]] + atomicAdd(&loc[ps[u]], 1);
        g_perm2[p] = e;
        int k0 = src[e]*Rr + et_inv[e];
        g_elist[0][atomicAdd(&g_cursor[0][k0], 1)] = e;
        int k1 = dst[e]*Rr + et_rel[e];
        g_elist[1][atomicAdd(&g_cursor[1][k1], 1)] = e;
    }
}

__global__ void k_invdiv() {
    int n = blockIdx.x*256 + threadIdx.x;
#pragma unroll
    for (int br = 0; br < 2; br++) {
        int c = 0;
        for (int r = 0; r < Rr; r++)
            if (g_rowptr[br][n*Rr+r+1] > g_rowptr[br][n*Rr+r]) c++;
        g_invdiv[br][n] = c ? 1.f/(float)c : 1.f;
    }
}

// ---------------- fused pair-binned edge GEMM + score ----------------
// 64x256 tile, 256 threads, 2 CTAs/SM, K-chunk=64 (8 chunks)
__global__ void __launch_bounds__(256,2) k_edge(const int* __restrict__ src,
        const int* __restrict__ dst, const float* __restrict__ ef,
        float* __restrict__ rel_out,
        const float* __restrict__ bias_sub, const float* __restrict__ bias_obj) {
    extern __shared__ char smem[];
    int bx = blockIdx.x;
    if (bx >= g_tileStart2[NPAIR]) return;
    int4 tp = g_tile[bx];
    int r1 = tp.x, r2 = tp.y, row0 = tp.z, rowEnd = tp.w;

    int tid = threadIdx.x;
    int* es  = (int*)(smem + SM2_ES);
    int* gsS = (int*)(smem + SM2_GSS);
    int* gsD = (int*)(smem + SM2_GSD);
    if (tid < 64) {
        int row = row0 + tid;
        if (row < rowEnd) { int e = g_perm2[row]; es[tid] = e; gsS[tid] = src[e]; gsD[tid] = dst[e]; }
        else { es[tid] = -1; gsS[tid] = 0; gsD[tid] = 0; }
    }
    __syncthreads();

    const __nv_bfloat16* __restrict__ W1h = g_Wt_hi[0] + (size_t)r1*Cc*Cc;
    const __nv_bfloat16* __restrict__ W2h = g_Wt_hi[1] + (size_t)r2*Cc*Cc;

    auto load_chunk = [&](int ch, int st){
        char* base = smem + SM2_BUF + st*SSTRIDE_E;
        __nv_bfloat16* AH = (__nv_bfloat16*)base;
        __nv_bfloat16* BH = (__nv_bfloat16*)(base + A_BYTES);
        int srcside = ch < 4;
        int k0 = (ch & 3)*64;
#pragma unroll
        for (int it = 0; it < 2; it++) {
            int i = it*256 + tid; int row = i >> 3, c16 = i & 7;
            int node = srcside ? gsS[row] : gsD[row];
            cpa16(smem_u32(AH + row*PADK + c16*8), g_nf_hi + (size_t)node*Cc + k0 + c16*8);
        }
        const __nv_bfloat16* Wh = srcside ? W1h : W2h;
#pragma unroll
        for (int it = 0; it < 8; it++) {
            int i = it*256 + tid; int row = i >> 3, c16 = i & 7;
            cpa16(smem_u32(BH + row*PADK + c16*8), Wh + (size_t)row*Cc + k0 + c16*8);
        }
        cpa_commit();
    };

    int lane = tid & 31, wid = tid >> 5;
    int gid = lane >> 2, tig = lane & 3;
    int wm = wid & 1, wn = wid >> 1;

    int a_row = (lane & 15);
    int a_koff = (lane >> 4) << 3;
    int b_row = (lane & 7) + (((lane >> 4) & 1) << 3);
    int b_koff = ((lane >> 3) & 1) << 3;

    float acc[2][8][4];
#pragma unroll
    for (int mt = 0; mt < 2; mt++)
#pragma unroll
        for (int nt = 0; nt < 8; nt++)
#pragma unroll
            for (int q = 0; q < 4; q++) acc[mt][nt][q] = 0.f;

    load_chunk(0, 0);
    for (int ch = 0; ch < 8; ch++) {
        if (ch < 7) { load_chunk(ch+1, (ch+1)&1); cpa_wait1(); }
        else cpa_wait0();
        __syncthreads();
        char* base = smem + SM2_BUF + (ch&1)*SSTRIDE_E;
        uint32_t aA = smem_u32(base);
        uint32_t aB = smem_u32(base + A_BYTES);
#pragma unroll
        for (int ks = 0; ks < 4; ks++) {
            int kc = ks*16;
            uint32_t ah[2][4];
#pragma unroll
            for (int mt = 0; mt < 2; mt++)
                ldsm4(ah[mt], aA + ((wm*32 + mt*16 + a_row)*PADK + kc + a_koff)*2);
            uint32_t bb[8][2];
#pragma unroll
            for (int ntp = 0; ntp < 4; ntp++) {
                uint32_t r[4];
                ldsm4(r, aB + ((wn*64 + ntp*16 + b_row)*PADK + kc + b_koff)*2);
                bb[2*ntp][0] = r[0]; bb[2*ntp][1] = r[1];
                bb[2*ntp+1][0] = r[2]; bb[2*ntp+1][1] = r[3];
            }
#pragma unroll
            for (int nt = 0; nt < 8; nt++)
#pragma unroll
                for (int mt = 0; mt < 2; mt++)
                    mma16816(acc[mt][nt], ah[mt], bb[nt][0], bb[nt][1]);
        }
        __syncthreads();
    }

    // epilogue: rel write (fp32 + bf16 mirror) + fused scores
    float* sc0 = (float*)(smem + SM2_BUF);
    float* sc1 = sc0 + 64;
    if (tid < 64) { sc0[tid] = 0.f; sc1[tid] = 0.f; }
    __syncthreads();

    const float* vs = g_v[0] + r2*Cc;
    const float* vo = g_v[1] + r1*Cc;
    int cbase = wn*64 + 2*tig;
#pragma unroll
    for (int mt = 0; mt < 2; mt++)
#pragma unroll
        for (int h = 0; h < 2; h++) {
            int row = wm*32 + mt*16 + h*8 + gid;
            int e = es[row];
            float s0 = 0.f, s1 = 0.f;
            if (e >= 0) {
                float* op = rel_out + (size_t)e*Cc + cbase;
                const float* efp = ef + (size_t)e*Cc + cbase;
                __nv_bfloat16* rb = g_relb + (size_t)e*Cc + cbase;
#pragma unroll
                for (int nt = 0; nt < 8; nt++) {
                    int c = cbase + nt*8;
                    float2 e2 = *(const float2*)(efp + nt*8);
                    float wx = e2.x + 0.5f*acc[mt][nt][h*2+0];
                    float wy = e2.y + 0.5f*acc[mt][nt][h*2+1];
                    *(float2*)(op + nt*8) = make_float2(wx, wy);
                    *(__nv_bfloat162*)(rb + nt*8) = __floats2bfloat162_rn(wx, wy);
                    s0 += wx*vs[c] + wy*vs[c+1];
                    s1 += wx*vo[c] + wy*vo[c+1];
                }
            }
            s0 += __shfl_xor_sync(0xffffffffu, s0, 1);
            s0 += __shfl_xor_sync(0xffffffffu, s0, 2);
            s1 += __shfl_xor_sync(0xffffffffu, s1, 1);
            s1 += __shfl_xor_sync(0xffffffffu, s1, 2);
            if (tig == 0 && e >= 0) {
                atomicAdd(&sc0[row], s0);
                atomicAdd(&sc1[row], s1);
            }
        }
    __syncthreads();
    if (tid < 64) {
        int e = es[tid];
        if (e >= 0) {
            float a = sc0[tid] + bias_sub[r2]; a = (a >= 0.f) ? a : 0.01f*a;
            float b = sc1[tid] + bias_obj[r1]; b = (b >= 0.f) ? b : 0.01f*b;
            g_scores[0][e] = a;
            g_scores[1][e] = b;
        }
    }
}

// P fill (both branches): invdiv-scaled softmax-weighted sums from bf16 rel, single pass
__global__ void k_pfill() {
    int w = blockIdx.x*8 + (threadIdx.x >> 5);
    int lane = threadIdx.x & 31;
    int br = (w >= NK) ? 1 : 0;
    int key = w - br*NK;
    if (w >= 2*NK) return;
    int lo = g_rowptr[br][key], hi = g_rowptr[br][key+1];
    float2 acc[4];
#pragma unroll
    for (int j = 0; j < 4; j++) acc[j] = make_float2(0.f, 0.f);
    if (lo < hi) {
        float den = 0.f;
        for (int p = lo; p < hi; p++) {
            int e = g_elist[br][p];
            float wt = expf(g_scores[br][e]);
            den += wt;
            const __nv_bfloat162* x = (const __nv_bfloat162*)(g_relb + (size_t)e*Cc);
#pragma unroll
            for (int j = 0; j < 4; j++) {
                __nv_bfloat162 v = x[lane + 32*j];
                acc[j].x += wt*__low2float(v);
                acc[j].y += wt*__high2float(v);
            }
        }
        float inv = g_invdiv[br][key/Rr]/den;
#pragma unroll
        for (int j = 0; j < 4; j++) { acc[j].x *= inv; acc[j].y *= inv; }
    }
    __nv_bfloat162* Ph = (__nv_bfloat162*)(g_Ph[br] + (size_t)key*Cc);
#pragma unroll
    for (int j = 0; j < 4; j++) Ph[lane + 32*j] = __floats2bfloat162_rn(acc[j].x, acc[j].y);
}

// ---------------- fused agg GEMM: out = nf + 0.5*([P0,P1] @ [W2;W3])  (K=4608) ----------------
// 64x256 tile, 256 threads, 2 CTAs/SM, K-chunk=64 (72 chunks)
__global__ void __launch_bounds__(256,2) k_g3(const float* __restrict__ nf,
                                              float* __restrict__ node_out) {
    extern __shared__ char smem[];
    int n0 = blockIdx.x*TILE_M;
    int tid = threadIdx.x;

    auto load_chunk = [&](int ch, int st){
        char* base = smem + st*SSTRIDE_G;
        __nv_bfloat16* AH = (__nv_bfloat16*)base;
        __nv_bfloat16* BH = (__nv_bfloat16*)(base + A_BYTES);
        int brs = ch >= 36;
        int kk = (brs ? ch-36 : ch)*64;
#pragma unroll
        for (int it = 0; it < 2; it++) {
            int i = it*256 + tid; int row = i >> 3, c16 = i & 7;
            cpa16(smem_u32(AH + row*PADK + c16*8),
                  g_Ph[brs] + (size_t)(n0+row)*(Rr*Cc) + kk + c16*8);
        }
        int rb = kk >> 8, c0 = kk & 255;
        const __nv_bfloat16* Wh = g_Wt_hi[2+brs] + (size_t)rb*Cc*Cc + c0;
#pragma unroll
        for (int it = 0; it < 8; it++) {
            int i = it*256 + tid; int row = i >> 3, c16 = i & 7;
            cpa16(smem_u32(BH + row*PADK + c16*8), Wh + (size_t)row*Cc + c16*8);
        }
        cpa_commit();
    };

    int lane = tid & 31, wid = tid >> 5;
    int gid = lane >> 2, tig = lane & 3;
    int wm = wid & 1, wn = wid >> 1;

    int a_row = (lane & 15);
    int a_koff = (lane >> 4) << 3;
    int b_row = (lane & 7) + (((lane >> 4) & 1) << 3);
    int b_koff = ((lane >> 3) & 1) << 3;

    float acc[2][8][4];
#pragma unroll
    for (int mt = 0; mt < 2; mt++)
#pragma unroll
        for (int nt = 0; nt < 8; nt++)
#pragma unroll
            for (int q = 0; q < 4; q++) acc[mt][nt][q] = 0.f;

    const int NCH = 72;
    load_chunk(0, 0);
    for (int ch = 0; ch < NCH; ch++) {
        if (ch < NCH-1) { load_chunk(ch+1, (ch+1)&1); cpa_wait1(); }
        else cpa_wait0();
        __syncthreads();
        char* base = smem + (ch&1)*SSTRIDE_G;
        uint32_t aA = smem_u32(base);
        uint32_t aB = smem_u32(base + A_BYTES);
#pragma unroll
        for (int ks = 0; ks < 4; ks++) {
            int kc = ks*16;
            uint32_t ah[2][4];
#pragma unroll
            for (int mt = 0; mt < 2; mt++)
                ldsm4(ah[mt], aA + ((wm*32 + mt*16 + a_row)*PADK + kc + a_koff)*2);
            uint32_t bb[8][2];
#pragma unroll
            for (int ntp = 0; ntp < 4; ntp++) {
                uint32_t r[4];
                ldsm4(r, aB + ((wn*64 + ntp*16 + b_row)*PADK + kc + b_koff)*2);
                bb[2*ntp][0] = r[0]; bb[2*ntp][1] = r[1];
                bb[2*ntp+1][0] = r[2]; bb[2*ntp+1][1] = r[3];
            }
#pragma unroll
            for (int nt = 0; nt < 8; nt++)
#pragma unroll
                for (int mt = 0; mt < 2; mt++)
                    mma16816(acc[mt][nt], ah[mt], bb[nt][0], bb[nt][1]);
        }
        __syncthreads();
    }

    int cbase = wn*64 + 2*tig;
#pragma unroll
    for (int mt = 0; mt < 2; mt++)
#pragma unroll
        for (int h = 0; h < 2; h++) {
            int n = n0 + wm*32 + mt*16 + h*8 + gid;
            float* op = node_out + (size_t)n*Cc + cbase;
            const float* nfp = nf + (size_t)n*Cc + cbase;
#pragma unroll
            for (int nt = 0; nt < 8; nt++) {
                float2 b2 = *(const float2*)(nfp + nt*8);
                float2 w;
                w.x = b2.x + 0.5f*acc[mt][nt][h*2+0];
                w.y = b2.y + 0.5f*acc[mt][nt][h*2+1];
                *(float2*)(op + nt*8) = w;
            }
        }
}

extern "C" void kernel_launch(void* const* d_in, const int* in_sizes, int n_in,
                              void* d_out, int out_size) {
    const int* ei      = (const int*)d_in[0];
    const int* src     = ei;
    const int* dst     = ei + Ee;
    const float* nf    = (const float*)d_in[1];
    const float* ef    = (const float*)d_in[2];
    const int* et_rel  = (const int*)d_in[3];
    const int* et_inv  = (const int*)d_in[4];
    const float* s2r_b = (const float*)d_in[6];
    const float* s2r_a = (const float*)d_in[7];
    const float* o2r_b = (const float*)d_in[8];
    const float* o2r_a = (const float*)d_in[9];
    const float* r2s_b = (const float*)d_in[10];
    const float* r2s_a = (const float*)d_in[11];
    const float* r2s_w = (const float*)d_in[12];
    const float* r2s_bias = (const float*)d_in[13];
    const float* r2o_b = (const float*)d_in[14];
    const float* r2o_a = (const float*)d_in[15];
    const float* r2o_w = (const float*)d_in[16];
    const float* r2o_bias = (const float*)d_in[17];

    float* node_out = (float*)d_out;
    float* rel_out  = node_out + (size_t)Nn*Cc;

    cudaFuncSetAttribute(k_edge, cudaFuncAttributeMaxDynamicSharedMemorySize, SM2_TOTAL);
    cudaFuncSetAttribute(k_g3, cudaFuncAttributeMaxDynamicSharedMemorySize, SM3_TOTAL);

    k_initnf<<<(Nn*Cc)/256, 256>>>(nf);
    k_wtb<<<4*Rr*64, 256>>>(s2r_b, s2r_a, o2r_b, o2r_a, r2s_b, r2s_a, r2o_b, r2o_a);
    k_vb<<<2*Rr, 256>>>(r2s_b, r2s_a, r2s_w, r2o_b, r2o_a, r2o_w);
    k_hist<<<256, 256>>>(src, dst, et_rel, et_inv);
    k_smallscan<<<1, 32>>>();
    k_tilefill<<<NPAIR, 128>>>();
    k_scan1<<<2*NCHUNK, 256>>>();
    k_scan2<<<1, 32>>>();
    k_scan3<<<2*NCHUNK, 256>>>();
    k_scatter<<<256, 256>>>(src, dst, et_rel, et_inv);
    k_invdiv<<<Nn/256, 256>>>();

    k_edge<<<TILES2, 256, SM2_TOTAL>>>(src, dst, ef, rel_out, r2s_bias, r2o_bias);
    k_pfill<<<2*NK/8, 256>>>();
    k_g3<<<Nn/TILE_M, 256, SM3_TOTAL>>>(nf, node_out);
}